// round 7
// baseline (speedup 1.0000x reference)
#include <cuda_runtime.h>
#include <cuda_fp16.h>
#include <mma.h>
using namespace nvcuda;

#define D 64
#define N_MAX 50048
#define E_MAX 800000
#define SCAN_BLK 256
#define NB_MAX 200

// ---------------- device scratch (static, allowed) ----------------
// Packed half tables: row = 128 halfs = 256B.
//   g_q[node] = [q_alpha(64) | q_beta(64)]
//   g_k[node] = [k_alpha(64) | k_beta(64)]
//   g_v[node] = [v_t(64)     | v_x(64)   ]
__device__ __align__(16) __half g_q[N_MAX * 128];
__device__ __align__(16) __half g_k[N_MAX * 128];
__device__ __align__(16) __half g_v[N_MAX * 128];

// CSR-style bucketing of edges by destination (row)
__device__ int g_cnt[N_MAX];      // in-degree (zero at load; scan re-zeros each call)
__device__ int g_start[N_MAX];    // exclusive prefix sum
__device__ int g_cursor[N_MAX];   // fill cursor (== end after scatter)
__device__ int g_sc[E_MAX];       // col index per bucketed edge
__device__ unsigned long long g_state[NB_MAX];  // lookback: status(hi32)|value(lo32)

// ---------------- kernel 1: projections via HMMA (wmma) ----------------
struct PArgs {
    const float* in[6];
    const float* W[6];
    const float* b[6];
};

#define LDA 72
#define LDW 72
#define LDC 68

__global__ __launch_bounds__(256) void proj_kernel(PArgs a, int n) {
    __shared__ __align__(16) char sbuf[34816];
    __half* sA = (__half*)sbuf;
    __half* sW = (__half*)(sbuf + 18432);
    float*  sC = (float*)sbuf;

    int p = blockIdx.y;
    const float* in   = a.in[p];
    const float* W    = a.W[p];
    const float* bias = a.b[p];
    __half* outp;
    int coloff;
    switch (p) {
        case 0: outp = g_q; coloff = 0;  break;
        case 1: outp = g_k; coloff = 0;  break;
        case 2: outp = g_q; coloff = 64; break;
        case 3: outp = g_k; coloff = 64; break;
        case 4: outp = g_v; coloff = 0;  break;
        default: outp = g_v; coloff = 64; break;
    }

    int tid  = threadIdx.x;
    int base = blockIdx.x * 128;

    #pragma unroll
    for (int t = 0; t < 8; t++) {
        int idx = tid + t * 256;
        int row = idx >> 4, c4 = idx & 15;
        int g = base + row;
        float4 f = (g < n) ? ((const float4*)in)[(size_t)g * 16 + c4]
                           : make_float4(0.f, 0.f, 0.f, 0.f);
        __half2 h0 = __floats2half2_rn(f.x, f.y);
        __half2 h1 = __floats2half2_rn(f.z, f.w);
        __half2* d = (__half2*)&sA[row * LDA + c4 * 4];
        d[0] = h0; d[1] = h1;
    }
    #pragma unroll
    for (int t = 0; t < 4; t++) {
        int idx = tid + t * 256;
        int row = idx >> 4, c4 = idx & 15;
        float4 f = ((const float4*)W)[idx];
        __half2 h0 = __floats2half2_rn(f.x, f.y);
        __half2 h1 = __floats2half2_rn(f.z, f.w);
        __half2* d = (__half2*)&sW[row * LDW + c4 * 4];
        d[0] = h0; d[1] = h1;
    }
    __syncthreads();

    int w  = tid >> 5;
    int wm = w & 3, wn = w >> 2;

    wmma::fragment<wmma::accumulator, 16, 16, 16, float> c[2][2];
    #pragma unroll
    for (int i = 0; i < 2; i++)
        #pragma unroll
        for (int jj = 0; jj < 2; jj++)
            wmma::fill_fragment(c[i][jj], 0.f);

    #pragma unroll
    for (int k0 = 0; k0 < 64; k0 += 16) {
        wmma::fragment<wmma::matrix_a, 16, 16, 16, __half, wmma::row_major> af[2];
        wmma::fragment<wmma::matrix_b, 16, 16, 16, __half, wmma::col_major> bf[2];
        #pragma unroll
        for (int i = 0; i < 2; i++)
            wmma::load_matrix_sync(af[i], &sA[(wm * 32 + i * 16) * LDA + k0], LDA);
        #pragma unroll
        for (int jj = 0; jj < 2; jj++)
            wmma::load_matrix_sync(bf[jj], &sW[(wn * 32 + jj * 16) * LDW + k0], LDW);
        #pragma unroll
        for (int i = 0; i < 2; i++)
            #pragma unroll
            for (int jj = 0; jj < 2; jj++)
                wmma::mma_sync(c[i][jj], af[i], bf[jj], c[i][jj]);
    }
    __syncthreads();

    #pragma unroll
    for (int i = 0; i < 2; i++)
        #pragma unroll
        for (int jj = 0; jj < 2; jj++)
            wmma::store_matrix_sync(&sC[(wm * 32 + i * 16) * LDC + wn * 32 + jj * 16],
                                    c[i][jj], LDC, wmma::mem_row_major);
    __syncthreads();

    #pragma unroll
    for (int t = 0; t < 16; t++) {
        int i = tid + t * 256;
        int row = i >> 5, pr = i & 31;
        int g = base + row;
        if (g < n) {
            float f0 = sC[row * LDC + 2 * pr];
            float f1 = sC[row * LDC + 2 * pr + 1];
            if (bias) { f0 += bias[2 * pr]; f1 += bias[2 * pr + 1]; }
            *(__half2*)&outp[(size_t)g * 128 + coloff + 2 * pr] =
                __floats2half2_rn(f0, f1);
        }
    }
}

// ---------------- kernel 2: histogram + reset lookback state ------------
__global__ void hist_kernel(const int* __restrict__ ei, int e, int n, int nb) {
    int i = blockIdx.x * blockDim.x + threadIdx.x;
    if (i < nb) g_state[i] = 0ULL;
    if (i >= e) return;
    int r = __ldg(&ei[i]);
    if ((unsigned)r < (unsigned)n) atomicAdd(&g_cnt[r], 1);
}

// ---------------- single-pass decoupled-lookback scan -------------------
__device__ __forceinline__ int block_scan_excl(int v, int tid, int* s_w, int* s_tot) {
    int x = v;
    #pragma unroll
    for (int o = 1; o < 32; o <<= 1) {
        int t = __shfl_up_sync(0xFFFFFFFFu, x, o);
        if ((tid & 31) >= o) x += t;
    }
    if ((tid & 31) == 31) s_w[tid >> 5] = x;
    __syncthreads();
    if (tid < 8) {
        int w = s_w[tid];
        #pragma unroll
        for (int o = 1; o < 8; o <<= 1) {
            int t = __shfl_up_sync(0xFFu, w, o);
            if (tid >= o) w += t;
        }
        s_w[tid] = w;
        if (tid == 7) *s_tot = w;
    }
    __syncthreads();
    int warp = tid >> 5;
    int woff = (warp == 0) ? 0 : s_w[warp - 1];
    return woff + x - v;
}

// All 196 blocks co-resident -> lookback spin cannot deadlock.
__global__ __launch_bounds__(SCAN_BLK) void scan_fused_kernel(int n) {
    __shared__ int s_w[8];
    __shared__ int s_tot;
    __shared__ int s_prefix;
    int bid = blockIdx.x;
    int tid = threadIdx.x;
    int i = bid * SCAN_BLK + tid;

    int v = (i < n) ? g_cnt[i] : 0;
    if (i < n) g_cnt[i] = 0;                 // reset for next graph replay
    int excl = block_scan_excl(v, tid, s_w, &s_tot);

    if (tid == 0) {
        int run = 0;
        if (bid == 0) {
            atomicExch(&g_state[0], (2ULL << 32) | (unsigned)s_tot);
        } else {
            atomicExch(&g_state[bid], (1ULL << 32) | (unsigned)s_tot);
            int lb = bid - 1;
            while (true) {
                unsigned long long s = atomicAdd(&g_state[lb], 0ULL);
                unsigned st = (unsigned)(s >> 32);
                if (st == 0) continue;       // not published yet
                run += (int)(unsigned)(s & 0xFFFFFFFFu);
                if (st == 2) break;          // inclusive prefix found
                lb--;
            }
            atomicExch(&g_state[bid], (2ULL << 32) | (unsigned)(run + s_tot));
        }
        s_prefix = run;
    }
    __syncthreads();

    int g = excl + s_prefix;
    if (i < n) { g_start[i] = g; g_cursor[i] = g; }
}

// ---------------- kernel 4: bucket the col indices by destination --------
__global__ void scatter_kernel(const int* __restrict__ ei, int e, int n) {
    int i = blockIdx.x * blockDim.x + threadIdx.x;
    if (i >= e) return;
    int r = __ldg(&ei[i]);
    int c = __ldg(&ei[e + i]);
    if ((unsigned)r >= (unsigned)n || (unsigned)c >= (unsigned)n) return;
    int pos = atomicAdd(&g_cursor[r], 1);
    g_sc[pos] = c;
}

// ---------------- kernel 5: per-node gather + softmax + aggregate --------
// One warp per destination node, 4 edges in flight (4 independent shfl
// chains), depth-4 prefetch. Lanes 0-15 alpha/t, 16-31 beta/x.
// Invalid slots hold zeros or stale *finite* data; their ex is forced to 0.
__global__ __launch_bounds__(256) void node_kernel(float* __restrict__ out, int n) {
    int warp = (blockIdx.x * blockDim.x + threadIdx.x) >> 5;
    int lane = threadIdx.x & 31;
    if (warp >= n) return;
    int r = warp;

    int j    = g_start[r];
    int jend = g_cursor[r];

    uint2 qu = ((const uint2*)(g_q + (size_t)r * 128))[lane];
    float2 q0 = __half22float2(*(const __half2*)&qu.x);
    float2 q1 = __half22float2(*(const __half2*)&qu.y);

    float4 acc = make_float4(0.f, 0.f, 0.f, 0.f);
    float  den = 0.f;

    uint2 kp[4], vp[4];
    #pragma unroll
    for (int s = 0; s < 4; s++) { kp[s] = make_uint2(0, 0); vp[s] = make_uint2(0, 0); }
    #pragma unroll
    for (int s = 0; s < 4; s++) {
        if (j + s < jend) {
            int c = __ldg(&g_sc[j + s]);
            kp[s] = ((const uint2*)(g_k + (size_t)c * 128))[lane];
            vp[s] = ((const uint2*)(g_v + (size_t)c * 128))[lane];
        }
    }

    while (j < jend) {
        uint2 kc[4], vc[4];
        #pragma unroll
        for (int s = 0; s < 4; s++) { kc[s] = kp[s]; vc[s] = vp[s]; }
        int rem = jend - j;
        int jn = j + 4;
        #pragma unroll
        for (int s = 0; s < 4; s++) {
            if (jn + s < jend) {
                int c = __ldg(&g_sc[jn + s]);
                kp[s] = ((const uint2*)(g_k + (size_t)c * 128))[lane];
                vp[s] = ((const uint2*)(g_v + (size_t)c * 128))[lane];
            }
        }
        j = jn;

        float p[4];
        #pragma unroll
        for (int s = 0; s < 4; s++) {
            float2 a0 = __half22float2(*(const __half2*)&kc[s].x);
            float2 a1 = __half22float2(*(const __half2*)&kc[s].y);
            p[s] = q0.x * a0.x + q0.y * a0.y + q1.x * a1.x + q1.y * a1.y;
        }

        // four independent 16-lane reductions, interleaved for ILP
        #pragma unroll
        for (int o = 1; o <= 8; o <<= 1) {
            p[0] += __shfl_xor_sync(0xFFFFFFFFu, p[0], o);
            p[1] += __shfl_xor_sync(0xFFFFFFFFu, p[1], o);
            p[2] += __shfl_xor_sync(0xFFFFFFFFu, p[2], o);
            p[3] += __shfl_xor_sync(0xFFFFFFFFu, p[3], o);
        }

        float ex[4];
        #pragma unroll
        for (int s = 0; s < 4; s++)
            ex[s] = (rem > s) ? __expf(p[s] * 0.125f) : 0.f;
        den += (ex[0] + ex[1]) + (ex[2] + ex[3]);

        #pragma unroll
        for (int s = 0; s < 4; s++) {
            float2 b0 = __half22float2(*(const __half2*)&vc[s].x);
            float2 b1 = __half22float2(*(const __half2*)&vc[s].y);
            acc.x = fmaf(ex[s], b0.x, acc.x);
            acc.y = fmaf(ex[s], b0.y, acc.y);
            acc.z = fmaf(ex[s], b1.x, acc.z);
            acc.w = fmaf(ex[s], b1.y, acc.w);
        }
    }

    float inv = (den > 0.f) ? __frcp_rn(den) : 0.f;
    acc.x *= inv; acc.y *= inv; acc.z *= inv; acc.w *= inv;

    int totD = n * D;
    if (lane < 16) {   // t-message -> out_t
        *(float4*)&out[totD + r * D + 4 * lane] = acc;
    } else {           // x-message -> out_x
        *(float4*)&out[r * D + 4 * (lane - 16)] = acc;
    }
}

// ---------------- launch ----------------
extern "C" void kernel_launch(void* const* d_in, const int* in_sizes, int n_in,
                              void* d_out, int out_size) {
    const float* x_src = (const float*)d_in[0];
    const float* x_tgt = (const float*)d_in[1];
    const float* t_src = (const float*)d_in[2];
    const float* t_tgt = (const float*)d_in[3];
    const int*   ei    = (const int*)d_in[4];
    const float* W_x  = (const float*)d_in[5];
    const float* W_t  = (const float*)d_in[6];
    const float* Ka_W = (const float*)d_in[7];
    const float* Ka_b = (const float*)d_in[8];
    const float* Qa_W = (const float*)d_in[9];
    const float* Qa_b = (const float*)d_in[10];
    const float* Kb_W = (const float*)d_in[11];
    const float* Kb_b = (const float*)d_in[12];
    const float* Qb_W = (const float*)d_in[13];
    const float* Qb_b = (const float*)d_in[14];

    int n = in_sizes[0] / D;      // 50000
    int e = in_sizes[4] / 2;      // 800000

    PArgs pa;
    pa.in[0] = t_tgt; pa.W[0] = Qa_W; pa.b[0] = Qa_b;    // q_alpha
    pa.in[1] = t_src; pa.W[1] = Ka_W; pa.b[1] = Ka_b;    // k_alpha
    pa.in[2] = x_tgt; pa.W[2] = Qb_W; pa.b[2] = Qb_b;    // q_beta
    pa.in[3] = x_src; pa.W[3] = Kb_W; pa.b[3] = Kb_b;    // k_beta
    pa.in[4] = t_src; pa.W[4] = W_t;  pa.b[4] = nullptr; // v_t
    pa.in[5] = x_src; pa.W[5] = W_x;  pa.b[5] = nullptr; // v_x

    int nb = (n + SCAN_BLK - 1) / SCAN_BLK;   // 196

    hist_kernel<<<(e + 255) / 256, 256>>>(ei, e, n, nb);
    proj_kernel<<<dim3((n + 127) / 128, 6), 256>>>(pa, n);
    scan_fused_kernel<<<nb, SCAN_BLK>>>(n);
    scatter_kernel<<<(e + 255) / 256, 256>>>(ei, e, n);
    node_kernel<<<(n * 32 + 255) / 256, 256>>>((float*)d_out, n);
}

// round 9
// speedup vs baseline: 1.0161x; 1.0161x over previous
#include <cuda_runtime.h>
#include <cuda_fp16.h>
#include <mma.h>
using namespace nvcuda;

#define D 64
#define N_MAX 50048
#define E_MAX 800000
#define SCAN_BLK 256

// ---------------- device scratch (static, allowed) ----------------
// Packed half tables: row = 128 halfs = 256B.
//   g_q[node] = [q_alpha(64) | q_beta(64)]
//   g_k[node] = [k_alpha(64) | k_beta(64)]
//   g_v[node] = [v_t(64)     | v_x(64)   ]
__device__ __align__(16) __half g_q[N_MAX * 128];
__device__ __align__(16) __half g_k[N_MAX * 128];
__device__ __align__(16) __half g_v[N_MAX * 128];

// CSR-style bucketing of edges by destination (row)
__device__ int g_cnt[N_MAX];      // in-degree (zero at load; scan1 re-zeros)
__device__ int g_start[N_MAX];    // exclusive prefix sum
__device__ int g_cursor[N_MAX];   // fill cursor (== end after scatter)
__device__ int g_sc[E_MAX];       // col index per bucketed edge
__device__ int g_bsum[(N_MAX + SCAN_BLK - 1) / SCAN_BLK + 1];

// ---------------- kernel 1: projections via HMMA (wmma) ----------------
struct PArgs {
    const float* in[6];
    const float* W[6];
    const float* b[6];
};

#define LDA 72
#define LDW 72
#define LDC 68

__global__ __launch_bounds__(256) void proj_kernel(PArgs a, int n) {
    __shared__ __align__(16) char sbuf[34816];
    __half* sA = (__half*)sbuf;
    __half* sW = (__half*)(sbuf + 18432);
    float*  sC = (float*)sbuf;

    int p = blockIdx.y;
    const float* in   = a.in[p];
    const float* W    = a.W[p];
    const float* bias = a.b[p];
    __half* outp;
    int coloff;
    switch (p) {
        case 0: outp = g_q; coloff = 0;  break;
        case 1: outp = g_k; coloff = 0;  break;
        case 2: outp = g_q; coloff = 64; break;
        case 3: outp = g_k; coloff = 64; break;
        case 4: outp = g_v; coloff = 0;  break;
        default: outp = g_v; coloff = 64; break;
    }

    int tid  = threadIdx.x;
    int base = blockIdx.x * 128;

    #pragma unroll
    for (int t = 0; t < 8; t++) {
        int idx = tid + t * 256;
        int row = idx >> 4, c4 = idx & 15;
        int g = base + row;
        float4 f = (g < n) ? ((const float4*)in)[(size_t)g * 16 + c4]
                           : make_float4(0.f, 0.f, 0.f, 0.f);
        __half2 h0 = __floats2half2_rn(f.x, f.y);
        __half2 h1 = __floats2half2_rn(f.z, f.w);
        __half2* d = (__half2*)&sA[row * LDA + c4 * 4];
        d[0] = h0; d[1] = h1;
    }
    #pragma unroll
    for (int t = 0; t < 4; t++) {
        int idx = tid + t * 256;
        int row = idx >> 4, c4 = idx & 15;
        float4 f = ((const float4*)W)[idx];
        __half2 h0 = __floats2half2_rn(f.x, f.y);
        __half2 h1 = __floats2half2_rn(f.z, f.w);
        __half2* d = (__half2*)&sW[row * LDW + c4 * 4];
        d[0] = h0; d[1] = h1;
    }
    __syncthreads();

    int w  = tid >> 5;
    int wm = w & 3, wn = w >> 2;

    wmma::fragment<wmma::accumulator, 16, 16, 16, float> c[2][2];
    #pragma unroll
    for (int i = 0; i < 2; i++)
        #pragma unroll
        for (int jj = 0; jj < 2; jj++)
            wmma::fill_fragment(c[i][jj], 0.f);

    #pragma unroll
    for (int k0 = 0; k0 < 64; k0 += 16) {
        wmma::fragment<wmma::matrix_a, 16, 16, 16, __half, wmma::row_major> af[2];
        wmma::fragment<wmma::matrix_b, 16, 16, 16, __half, wmma::col_major> bf[2];
        #pragma unroll
        for (int i = 0; i < 2; i++)
            wmma::load_matrix_sync(af[i], &sA[(wm * 32 + i * 16) * LDA + k0], LDA);
        #pragma unroll
        for (int jj = 0; jj < 2; jj++)
            wmma::load_matrix_sync(bf[jj], &sW[(wn * 32 + jj * 16) * LDW + k0], LDW);
        #pragma unroll
        for (int i = 0; i < 2; i++)
            #pragma unroll
            for (int jj = 0; jj < 2; jj++)
                wmma::mma_sync(c[i][jj], af[i], bf[jj], c[i][jj]);
    }
    __syncthreads();

    #pragma unroll
    for (int i = 0; i < 2; i++)
        #pragma unroll
        for (int jj = 0; jj < 2; jj++)
            wmma::store_matrix_sync(&sC[(wm * 32 + i * 16) * LDC + wn * 32 + jj * 16],
                                    c[i][jj], LDC, wmma::mem_row_major);
    __syncthreads();

    #pragma unroll
    for (int t = 0; t < 16; t++) {
        int i = tid + t * 256;
        int row = i >> 5, pr = i & 31;
        int g = base + row;
        if (g < n) {
            float f0 = sC[row * LDC + 2 * pr];
            float f1 = sC[row * LDC + 2 * pr + 1];
            if (bias) { f0 += bias[2 * pr]; f1 += bias[2 * pr + 1]; }
            *(__half2*)&outp[(size_t)g * 128 + coloff + 2 * pr] =
                __floats2half2_rn(f0, f1);
        }
    }
}

// ---------------- kernel 2: histogram, 4 edges per thread (MLP) ---------
// stride == total launched threads -> the 4 index sets are disjoint.
__global__ void hist_kernel(const int* __restrict__ ei, int e, int n, int stride) {
    int i = blockIdx.x * blockDim.x + threadIdx.x;
    int r0 = (i              < e) ? __ldg(&ei[i])              : -1;
    int r1 = (i + stride     < e) ? __ldg(&ei[i + stride])     : -1;
    int r2 = (i + 2 * stride < e) ? __ldg(&ei[i + 2 * stride]) : -1;
    int r3 = (i + 3 * stride < e) ? __ldg(&ei[i + 3 * stride]) : -1;
    if ((unsigned)r0 < (unsigned)n) atomicAdd(&g_cnt[r0], 1);
    if ((unsigned)r1 < (unsigned)n) atomicAdd(&g_cnt[r1], 1);
    if ((unsigned)r2 < (unsigned)n) atomicAdd(&g_cnt[r2], 1);
    if ((unsigned)r3 < (unsigned)n) atomicAdd(&g_cnt[r3], 1);
}

// ---------------- two-level scan (3 kernels, measured ~10us) ------------
__device__ __forceinline__ int block_scan_excl(int v, int tid, int* s_w, int* s_tot) {
    int x = v;
    #pragma unroll
    for (int o = 1; o < 32; o <<= 1) {
        int t = __shfl_up_sync(0xFFFFFFFFu, x, o);
        if ((tid & 31) >= o) x += t;
    }
    if ((tid & 31) == 31) s_w[tid >> 5] = x;
    __syncthreads();
    if (tid < 8) {
        int w = s_w[tid];
        #pragma unroll
        for (int o = 1; o < 8; o <<= 1) {
            int t = __shfl_up_sync(0xFFu, w, o);
            if (tid >= o) w += t;
        }
        s_w[tid] = w;
        if (tid == 7) *s_tot = w;
    }
    __syncthreads();
    int warp = tid >> 5;
    int woff = (warp == 0) ? 0 : s_w[warp - 1];
    return woff + x - v;
}

__global__ __launch_bounds__(SCAN_BLK) void scan1_kernel(int n) {
    __shared__ int s_w[8];
    __shared__ int s_tot;
    int tid = threadIdx.x;
    int i = blockIdx.x * SCAN_BLK + tid;
    int v = (i < n) ? g_cnt[i] : 0;
    if (i < n) g_cnt[i] = 0;                 // reset for next graph replay
    int excl = block_scan_excl(v, tid, s_w, &s_tot);
    if (i < n) g_start[i] = excl;
    if (tid == 0) g_bsum[blockIdx.x] = s_tot;
}

__global__ __launch_bounds__(SCAN_BLK) void scan2_kernel(int nb) {
    __shared__ int s_w[8];
    __shared__ int s_tot;
    int tid = threadIdx.x;
    int v = (tid < nb) ? g_bsum[tid] : 0;
    int excl = block_scan_excl(v, tid, s_w, &s_tot);
    if (tid < nb) g_bsum[tid] = excl;
}

__global__ __launch_bounds__(SCAN_BLK) void scan3_kernel(int n) {
    int i = blockIdx.x * SCAN_BLK + threadIdx.x;
    if (i >= n) return;
    int g = g_start[i] + g_bsum[blockIdx.x];
    g_start[i]  = g;
    g_cursor[i] = g;
}

// ---------------- kernel 4: bucket cols, 4 edges per thread (MLP) -------
__global__ void scatter_kernel(const int* __restrict__ ei, int e, int n, int stride) {
    int i = blockIdx.x * blockDim.x + threadIdx.x;
    #pragma unroll
    for (int k = 0; k < 4; k++) {
        int idx = i + k * stride;
        if (idx < e) {
            int r = __ldg(&ei[idx]);
            int c = __ldg(&ei[e + idx]);
            if ((unsigned)r < (unsigned)n && (unsigned)c < (unsigned)n) {
                int pos = atomicAdd(&g_cursor[r], 1);
                g_sc[pos] = c;
            }
        }
    }
}

// ---------------- kernel 5: per-node gather + softmax + aggregate --------
// One warp per destination node, 4 edges in flight, depth-4 prefetch.
// Lanes 0-15 alpha/t, 16-31 beta/x. Invalid slots -> ex forced to 0.
__global__ __launch_bounds__(256) void node_kernel(float* __restrict__ out, int n) {
    int warp = (blockIdx.x * blockDim.x + threadIdx.x) >> 5;
    int lane = threadIdx.x & 31;
    if (warp >= n) return;
    int r = warp;

    int j    = g_start[r];
    int jend = g_cursor[r];

    uint2 qu = ((const uint2*)(g_q + (size_t)r * 128))[lane];
    float2 q0 = __half22float2(*(const __half2*)&qu.x);
    float2 q1 = __half22float2(*(const __half2*)&qu.y);

    float4 acc = make_float4(0.f, 0.f, 0.f, 0.f);
    float  den = 0.f;

    uint2 kp[4], vp[4];
    #pragma unroll
    for (int s = 0; s < 4; s++) { kp[s] = make_uint2(0, 0); vp[s] = make_uint2(0, 0); }
    #pragma unroll
    for (int s = 0; s < 4; s++) {
        if (j + s < jend) {
            int c = __ldg(&g_sc[j + s]);
            kp[s] = ((const uint2*)(g_k + (size_t)c * 128))[lane];
            vp[s] = ((const uint2*)(g_v + (size_t)c * 128))[lane];
        }
    }

    while (j < jend) {
        uint2 kc[4], vc[4];
        #pragma unroll
        for (int s = 0; s < 4; s++) { kc[s] = kp[s]; vc[s] = vp[s]; }
        int rem = jend - j;
        int jn = j + 4;
        #pragma unroll
        for (int s = 0; s < 4; s++) {
            if (jn + s < jend) {
                int c = __ldg(&g_sc[jn + s]);
                kp[s] = ((const uint2*)(g_k + (size_t)c * 128))[lane];
                vp[s] = ((const uint2*)(g_v + (size_t)c * 128))[lane];
            }
        }
        j = jn;

        float p[4];
        #pragma unroll
        for (int s = 0; s < 4; s++) {
            float2 a0 = __half22float2(*(const __half2*)&kc[s].x);
            float2 a1 = __half22float2(*(const __half2*)&kc[s].y);
            p[s] = q0.x * a0.x + q0.y * a0.y + q1.x * a1.x + q1.y * a1.y;
        }

        #pragma unroll
        for (int o = 1; o <= 8; o <<= 1) {
            p[0] += __shfl_xor_sync(0xFFFFFFFFu, p[0], o);
            p[1] += __shfl_xor_sync(0xFFFFFFFFu, p[1], o);
            p[2] += __shfl_xor_sync(0xFFFFFFFFu, p[2], o);
            p[3] += __shfl_xor_sync(0xFFFFFFFFu, p[3], o);
        }

        float ex[4];
        #pragma unroll
        for (int s = 0; s < 4; s++)
            ex[s] = (rem > s) ? __expf(p[s] * 0.125f) : 0.f;
        den += (ex[0] + ex[1]) + (ex[2] + ex[3]);

        #pragma unroll
        for (int s = 0; s < 4; s++) {
            float2 b0 = __half22float2(*(const __half2*)&vc[s].x);
            float2 b1 = __half22float2(*(const __half2*)&vc[s].y);
            acc.x = fmaf(ex[s], b0.x, acc.x);
            acc.y = fmaf(ex[s], b0.y, acc.y);
            acc.z = fmaf(ex[s], b1.x, acc.z);
            acc.w = fmaf(ex[s], b1.y, acc.w);
        }
    }

    float inv = (den > 0.f) ? __frcp_rn(den) : 0.f;
    acc.x *= inv; acc.y *= inv; acc.z *= inv; acc.w *= inv;

    int totD = n * D;
    if (lane < 16) {   // t-message -> out_t
        *(float4*)&out[totD + r * D + 4 * lane] = acc;
    } else {           // x-message -> out_x
        *(float4*)&out[r * D + 4 * (lane - 16)] = acc;
    }
}

// ---------------- launch ----------------
extern "C" void kernel_launch(void* const* d_in, const int* in_sizes, int n_in,
                              void* d_out, int out_size) {
    const float* x_src = (const float*)d_in[0];
    const float* x_tgt = (const float*)d_in[1];
    const float* t_src = (const float*)d_in[2];
    const float* t_tgt = (const float*)d_in[3];
    const int*   ei    = (const int*)d_in[4];
    const float* W_x  = (const float*)d_in[5];
    const float* W_t  = (const float*)d_in[6];
    const float* Ka_W = (const float*)d_in[7];
    const float* Ka_b = (const float*)d_in[8];
    const float* Qa_W = (const float*)d_in[9];
    const float* Qa_b = (const float*)d_in[10];
    const float* Kb_W = (const float*)d_in[11];
    const float* Kb_b = (const float*)d_in[12];
    const float* Qb_W = (const float*)d_in[13];
    const float* Qb_b = (const float*)d_in[14];

    int n = in_sizes[0] / D;      // 50000
    int e = in_sizes[4] / 2;      // 800000

    PArgs pa;
    pa.in[0] = t_tgt; pa.W[0] = Qa_W; pa.b[0] = Qa_b;    // q_alpha
    pa.in[1] = t_src; pa.W[1] = Ka_W; pa.b[1] = Ka_b;    // k_alpha
    pa.in[2] = x_tgt; pa.W[2] = Qb_W; pa.b[2] = Qb_b;    // q_beta
    pa.in[3] = x_src; pa.W[3] = Kb_W; pa.b[3] = Kb_b;    // k_beta
    pa.in[4] = t_src; pa.W[4] = W_t;  pa.b[4] = nullptr; // v_t
    pa.in[5] = x_src; pa.W[5] = W_x;  pa.b[5] = nullptr; // v_x

    int nb = (n + SCAN_BLK - 1) / SCAN_BLK;         // 196
    int eblocks = (e / 4 + 255) / 256;              // blocks for 4-wide edge kernels
    int stride  = eblocks * 256;                    // == total threads (disjoint sets)

    hist_kernel<<<eblocks, 256>>>(ei, e, n, stride);
    proj_kernel<<<dim3((n + 127) / 128, 6), 256>>>(pa, n);
    scan1_kernel<<<nb, SCAN_BLK>>>(n);
    scan2_kernel<<<1, SCAN_BLK>>>(nb);
    scan3_kernel<<<nb, SCAN_BLK>>>(n);
    scatter_kernel<<<eblocks, 256>>>(ei, e, n, stride);
    node_kernel<<<(n * 32 + 255) / 256, 256>>>((float*)d_out, n);
}

// round 10
// speedup vs baseline: 1.1048x; 1.0873x over previous
#include <cuda_runtime.h>
#include <cuda_fp16.h>
#include <mma.h>
using namespace nvcuda;

#define D 64
#define N_MAX 50048
#define E_MAX 800000
#define SCAN_BLK 256

// ---------------- device scratch (static, allowed) ----------------
// Packed half tables: row = 128 halfs = 256B.
//   g_q[node] = [q_alpha(64) | q_beta(64)]
//   g_k[node] = [k_alpha(64) | k_beta(64)]
//   g_v[node] = [v_t(64)     | v_x(64)   ]
__device__ __align__(16) __half g_q[N_MAX * 128];
__device__ __align__(16) __half g_k[N_MAX * 128];
__device__ __align__(16) __half g_v[N_MAX * 128];

// CSR-style bucketing of edges by destination (row)
__device__ int g_cnt[N_MAX];      // in-degree (zero at load; scan1 re-zeros)
__device__ int g_start[N_MAX];    // exclusive prefix sum
__device__ int g_cursor[N_MAX];   // fill cursor (== end after scatter)
__device__ int g_sc[E_MAX];       // col index per bucketed edge
__device__ int g_bsum[(N_MAX + SCAN_BLK - 1) / SCAN_BLK + 1];

// ---------------- kernel 1: projections via HMMA (wmma) ----------------
struct PArgs {
    const float* in[6];
    const float* W[6];
    const float* b[6];
};

#define LDA 72
#define LDW 72
#define LDC 68

__global__ __launch_bounds__(256) void proj_kernel(PArgs a, int n) {
    __shared__ __align__(16) char sbuf[34816];
    __half* sA = (__half*)sbuf;
    __half* sW = (__half*)(sbuf + 18432);
    float*  sC = (float*)sbuf;

    int p = blockIdx.y;
    const float* in   = a.in[p];
    const float* W    = a.W[p];
    const float* bias = a.b[p];
    __half* outp;
    int coloff;
    switch (p) {
        case 0: outp = g_q; coloff = 0;  break;
        case 1: outp = g_k; coloff = 0;  break;
        case 2: outp = g_q; coloff = 64; break;
        case 3: outp = g_k; coloff = 64; break;
        case 4: outp = g_v; coloff = 0;  break;
        default: outp = g_v; coloff = 64; break;
    }

    int tid  = threadIdx.x;
    int base = blockIdx.x * 128;

    #pragma unroll
    for (int t = 0; t < 8; t++) {
        int idx = tid + t * 256;
        int row = idx >> 4, c4 = idx & 15;
        int g = base + row;
        float4 f = (g < n) ? ((const float4*)in)[(size_t)g * 16 + c4]
                           : make_float4(0.f, 0.f, 0.f, 0.f);
        __half2 h0 = __floats2half2_rn(f.x, f.y);
        __half2 h1 = __floats2half2_rn(f.z, f.w);
        __half2* d = (__half2*)&sA[row * LDA + c4 * 4];
        d[0] = h0; d[1] = h1;
    }
    #pragma unroll
    for (int t = 0; t < 4; t++) {
        int idx = tid + t * 256;
        int row = idx >> 4, c4 = idx & 15;
        float4 f = ((const float4*)W)[idx];
        __half2 h0 = __floats2half2_rn(f.x, f.y);
        __half2 h1 = __floats2half2_rn(f.z, f.w);
        __half2* d = (__half2*)&sW[row * LDW + c4 * 4];
        d[0] = h0; d[1] = h1;
    }
    __syncthreads();

    int w  = tid >> 5;
    int wm = w & 3, wn = w >> 2;

    wmma::fragment<wmma::accumulator, 16, 16, 16, float> c[2][2];
    #pragma unroll
    for (int i = 0; i < 2; i++)
        #pragma unroll
        for (int jj = 0; jj < 2; jj++)
            wmma::fill_fragment(c[i][jj], 0.f);

    #pragma unroll
    for (int k0 = 0; k0 < 64; k0 += 16) {
        wmma::fragment<wmma::matrix_a, 16, 16, 16, __half, wmma::row_major> af[2];
        wmma::fragment<wmma::matrix_b, 16, 16, 16, __half, wmma::col_major> bf[2];
        #pragma unroll
        for (int i = 0; i < 2; i++)
            wmma::load_matrix_sync(af[i], &sA[(wm * 32 + i * 16) * LDA + k0], LDA);
        #pragma unroll
        for (int jj = 0; jj < 2; jj++)
            wmma::load_matrix_sync(bf[jj], &sW[(wn * 32 + jj * 16) * LDW + k0], LDW);
        #pragma unroll
        for (int i = 0; i < 2; i++)
            #pragma unroll
            for (int jj = 0; jj < 2; jj++)
                wmma::mma_sync(c[i][jj], af[i], bf[jj], c[i][jj]);
    }
    __syncthreads();

    #pragma unroll
    for (int i = 0; i < 2; i++)
        #pragma unroll
        for (int jj = 0; jj < 2; jj++)
            wmma::store_matrix_sync(&sC[(wm * 32 + i * 16) * LDC + wn * 32 + jj * 16],
                                    c[i][jj], LDC, wmma::mem_row_major);
    __syncthreads();

    #pragma unroll
    for (int t = 0; t < 16; t++) {
        int i = tid + t * 256;
        int row = i >> 5, pr = i & 31;
        int g = base + row;
        if (g < n) {
            float f0 = sC[row * LDC + 2 * pr];
            float f1 = sC[row * LDC + 2 * pr + 1];
            if (bias) { f0 += bias[2 * pr]; f1 += bias[2 * pr + 1]; }
            *(__half2*)&outp[(size_t)g * 128 + coloff + 2 * pr] =
                __floats2half2_rn(f0, f1);
        }
    }
}

// ---------------- kernel 2: histogram, 4 edges per thread (MLP) ---------
// stride == total launched threads -> the 4 index sets are disjoint.
__global__ void hist_kernel(const int* __restrict__ ei, int e, int n, int stride) {
    int i = blockIdx.x * blockDim.x + threadIdx.x;
    int r0 = (i              < e) ? __ldg(&ei[i])              : -1;
    int r1 = (i + stride     < e) ? __ldg(&ei[i + stride])     : -1;
    int r2 = (i + 2 * stride < e) ? __ldg(&ei[i + 2 * stride]) : -1;
    int r3 = (i + 3 * stride < e) ? __ldg(&ei[i + 3 * stride]) : -1;
    if ((unsigned)r0 < (unsigned)n) atomicAdd(&g_cnt[r0], 1);
    if ((unsigned)r1 < (unsigned)n) atomicAdd(&g_cnt[r1], 1);
    if ((unsigned)r2 < (unsigned)n) atomicAdd(&g_cnt[r2], 1);
    if ((unsigned)r3 < (unsigned)n) atomicAdd(&g_cnt[r3], 1);
}

// ---------------- two-level scan (3 kernels, measured ~10us) ------------
__device__ __forceinline__ int block_scan_excl(int v, int tid, int* s_w, int* s_tot) {
    int x = v;
    #pragma unroll
    for (int o = 1; o < 32; o <<= 1) {
        int t = __shfl_up_sync(0xFFFFFFFFu, x, o);
        if ((tid & 31) >= o) x += t;
    }
    if ((tid & 31) == 31) s_w[tid >> 5] = x;
    __syncthreads();
    if (tid < 8) {
        int w = s_w[tid];
        #pragma unroll
        for (int o = 1; o < 8; o <<= 1) {
            int t = __shfl_up_sync(0xFFu, w, o);
            if (tid >= o) w += t;
        }
        s_w[tid] = w;
        if (tid == 7) *s_tot = w;
    }
    __syncthreads();
    int warp = tid >> 5;
    int woff = (warp == 0) ? 0 : s_w[warp - 1];
    return woff + x - v;
}

__global__ __launch_bounds__(SCAN_BLK) void scan1_kernel(int n) {
    __shared__ int s_w[8];
    __shared__ int s_tot;
    int tid = threadIdx.x;
    int i = blockIdx.x * SCAN_BLK + tid;
    int v = (i < n) ? g_cnt[i] : 0;
    if (i < n) g_cnt[i] = 0;                 // reset for next graph replay
    int excl = block_scan_excl(v, tid, s_w, &s_tot);
    if (i < n) g_start[i] = excl;
    if (tid == 0) g_bsum[blockIdx.x] = s_tot;
}

__global__ __launch_bounds__(SCAN_BLK) void scan2_kernel(int nb) {
    __shared__ int s_w[8];
    __shared__ int s_tot;
    int tid = threadIdx.x;
    int v = (tid < nb) ? g_bsum[tid] : 0;
    int excl = block_scan_excl(v, tid, s_w, &s_tot);
    if (tid < nb) g_bsum[tid] = excl;
}

__global__ __launch_bounds__(SCAN_BLK) void scan3_kernel(int n) {
    int i = blockIdx.x * SCAN_BLK + threadIdx.x;
    if (i >= n) return;
    int g = g_start[i] + g_bsum[blockIdx.x];
    g_start[i]  = g;
    g_cursor[i] = g;
}

// ---------------- kernel 4: bucket cols, 4 edges per thread (MLP) -------
__global__ void scatter_kernel(const int* __restrict__ ei, int e, int n, int stride) {
    int i = blockIdx.x * blockDim.x + threadIdx.x;
    #pragma unroll
    for (int k = 0; k < 4; k++) {
        int idx = i + k * stride;
        if (idx < e) {
            int r = __ldg(&ei[idx]);
            int c = __ldg(&ei[e + idx]);
            if ((unsigned)r < (unsigned)n && (unsigned)c < (unsigned)n) {
                int pos = atomicAdd(&g_cursor[r], 1);
                g_sc[pos] = c;
            }
        }
    }
}

// ---------------- kernel 5: per-node gather + softmax + aggregate --------
// One warp per destination node, 2 edges in flight (R6 configuration —
// 4-wide blew register budget and cost ~14us of occupancy).
// Lanes 0-15 alpha/t, 16-31 beta/x. Invalid slots -> ex forced to 0.
__global__ __launch_bounds__(256) void node_kernel(float* __restrict__ out, int n) {
    int warp = (blockIdx.x * blockDim.x + threadIdx.x) >> 5;
    int lane = threadIdx.x & 31;
    if (warp >= n) return;
    int r = warp;

    int j    = g_start[r];
    int jend = g_cursor[r];

    uint2 qu = ((const uint2*)(g_q + (size_t)r * 128))[lane];
    float2 q0 = __half22float2(*(const __half2*)&qu.x);
    float2 q1 = __half22float2(*(const __half2*)&qu.y);

    float4 acc = make_float4(0.f, 0.f, 0.f, 0.f);
    float  den = 0.f;

    uint2 kA = make_uint2(0,0), vA = make_uint2(0,0);
    uint2 kB = make_uint2(0,0), vB = make_uint2(0,0);
    if (j < jend) {
        int c = __ldg(&g_sc[j]);
        kA = ((const uint2*)(g_k + (size_t)c * 128))[lane];
        vA = ((const uint2*)(g_v + (size_t)c * 128))[lane];
    }
    if (j + 1 < jend) {
        int c = __ldg(&g_sc[j + 1]);
        kB = ((const uint2*)(g_k + (size_t)c * 128))[lane];
        vB = ((const uint2*)(g_v + (size_t)c * 128))[lane];
    }

    while (j < jend) {
        uint2 k0 = kA, v0 = vA, k1 = kB, v1 = vB;
        int rem = jend - j;
        int jn = j + 2;
        if (jn < jend) {
            int c = __ldg(&g_sc[jn]);
            kA = ((const uint2*)(g_k + (size_t)c * 128))[lane];
            vA = ((const uint2*)(g_v + (size_t)c * 128))[lane];
        }
        if (jn + 1 < jend) {
            int c = __ldg(&g_sc[jn + 1]);
            kB = ((const uint2*)(g_k + (size_t)c * 128))[lane];
            vB = ((const uint2*)(g_v + (size_t)c * 128))[lane];
        }
        j = jn;

        float2 ka0 = __half22float2(*(const __half2*)&k0.x);
        float2 ka1 = __half22float2(*(const __half2*)&k0.y);
        float2 kb0 = __half22float2(*(const __half2*)&k1.x);
        float2 kb1 = __half22float2(*(const __half2*)&k1.y);

        float p0 = q0.x * ka0.x + q0.y * ka0.y + q1.x * ka1.x + q1.y * ka1.y;
        float p1 = q0.x * kb0.x + q0.y * kb0.y + q1.x * kb1.x + q1.y * kb1.y;

        // two independent 16-lane reductions, interleaved for ILP
        p0 += __shfl_xor_sync(0xFFFFFFFFu, p0, 1);
        p1 += __shfl_xor_sync(0xFFFFFFFFu, p1, 1);
        p0 += __shfl_xor_sync(0xFFFFFFFFu, p0, 2);
        p1 += __shfl_xor_sync(0xFFFFFFFFu, p1, 2);
        p0 += __shfl_xor_sync(0xFFFFFFFFu, p0, 4);
        p1 += __shfl_xor_sync(0xFFFFFFFFu, p1, 4);
        p0 += __shfl_xor_sync(0xFFFFFFFFu, p0, 8);
        p1 += __shfl_xor_sync(0xFFFFFFFFu, p1, 8);

        float ex0 = __expf(p0 * 0.125f);
        float ex1 = (rem > 1) ? __expf(p1 * 0.125f) : 0.f;
        den += ex0 + ex1;

        float2 va0 = __half22float2(*(const __half2*)&v0.x);
        float2 va1 = __half22float2(*(const __half2*)&v0.y);
        float2 vb0 = __half22float2(*(const __half2*)&v1.x);
        float2 vb1 = __half22float2(*(const __half2*)&v1.y);

        acc.x = fmaf(ex0, va0.x, fmaf(ex1, vb0.x, acc.x));
        acc.y = fmaf(ex0, va0.y, fmaf(ex1, vb0.y, acc.y));
        acc.z = fmaf(ex0, va1.x, fmaf(ex1, vb1.x, acc.z));
        acc.w = fmaf(ex0, va1.y, fmaf(ex1, vb1.y, acc.w));
    }

    float inv = (den > 0.f) ? __frcp_rn(den) : 0.f;
    acc.x *= inv; acc.y *= inv; acc.z *= inv; acc.w *= inv;

    int totD = n * D;
    if (lane < 16) {   // t-message -> out_t
        *(float4*)&out[totD + r * D + 4 * lane] = acc;
    } else {           // x-message -> out_x
        *(float4*)&out[r * D + 4 * (lane - 16)] = acc;
    }
}

// ---------------- launch ----------------
extern "C" void kernel_launch(void* const* d_in, const int* in_sizes, int n_in,
                              void* d_out, int out_size) {
    const float* x_src = (const float*)d_in[0];
    const float* x_tgt = (const float*)d_in[1];
    const float* t_src = (const float*)d_in[2];
    const float* t_tgt = (const float*)d_in[3];
    const int*   ei    = (const int*)d_in[4];
    const float* W_x  = (const float*)d_in[5];
    const float* W_t  = (const float*)d_in[6];
    const float* Ka_W = (const float*)d_in[7];
    const float* Ka_b = (const float*)d_in[8];
    const float* Qa_W = (const float*)d_in[9];
    const float* Qa_b = (const float*)d_in[10];
    const float* Kb_W = (const float*)d_in[11];
    const float* Kb_b = (const float*)d_in[12];
    const float* Qb_W = (const float*)d_in[13];
    const float* Qb_b = (const float*)d_in[14];

    int n = in_sizes[0] / D;      // 50000
    int e = in_sizes[4] / 2;      // 800000

    PArgs pa;
    pa.in[0] = t_tgt; pa.W[0] = Qa_W; pa.b[0] = Qa_b;    // q_alpha
    pa.in[1] = t_src; pa.W[1] = Ka_W; pa.b[1] = Ka_b;    // k_alpha
    pa.in[2] = x_tgt; pa.W[2] = Qb_W; pa.b[2] = Qb_b;    // q_beta
    pa.in[3] = x_src; pa.W[3] = Kb_W; pa.b[3] = Kb_b;    // k_beta
    pa.in[4] = t_src; pa.W[4] = W_t;  pa.b[4] = nullptr; // v_t
    pa.in[5] = x_src; pa.W[5] = W_x;  pa.b[5] = nullptr; // v_x

    int nb = (n + SCAN_BLK - 1) / SCAN_BLK;         // 196
    int eblocks = (e / 4 + 255) / 256;              // blocks for 4-wide edge kernels
    int stride  = eblocks * 256;                    // == total threads (disjoint sets)

    hist_kernel<<<eblocks, 256>>>(ei, e, n, stride);
    proj_kernel<<<dim3((n + 127) / 128, 6), 256>>>(pa, n);
    scan1_kernel<<<nb, SCAN_BLK>>>(n);
    scan2_kernel<<<1, SCAN_BLK>>>(nb);
    scan3_kernel<<<nb, SCAN_BLK>>>(n);
    scatter_kernel<<<eblocks, 256>>>(ei, e, n, stride);
    node_kernel<<<(n * 32 + 255) / 256, 256>>>((float*)d_out, n);
}

// round 11
// speedup vs baseline: 1.2326x; 1.1157x over previous
#include <cuda_runtime.h>
#include <cuda_fp16.h>
#include <mma.h>
using namespace nvcuda;

#define D 64
#define N_MAX 50048
#define E_MAX 800000
#define SCAN_BLK 256

// ---------------- device scratch (static, allowed) ----------------
// Packed half tables: row = 128 halfs = 256B.
//   g_q[node] = [q_alpha(64) | q_beta(64)]
//   g_k[node] = [k_alpha(64) | k_beta(64)]
//   g_v[node] = [v_t(64)     | v_x(64)   ]
__device__ __align__(16) __half g_q[N_MAX * 128];
__device__ __align__(16) __half g_k[N_MAX * 128];
__device__ __align__(16) __half g_v[N_MAX * 128];

// CSR-style bucketing of edges by destination (row).
// Bucket regions are allocated in ARBITRARY order (atomic ticket) — only
// disjointness matters, not node-id ordering.
__device__ int g_cnt[N_MAX];      // in-degree (zero at load; scan re-zeros)
__device__ int g_start[N_MAX];    // bucket base
__device__ int g_cursor[N_MAX];   // fill cursor (== bucket end after scatter)
__device__ int g_sc[E_MAX];       // col index per bucketed edge
__device__ int g_total;           // ticket counter (reset by hist slice)

// ---------------- kernel 1: projections via HMMA + fused histogram ------
// blockIdx.y in 0..5: one projection each (tensor-core bound).
// blockIdx.y == 6:    edge histogram (atomic/latency bound) — hides under
//                     the tensor work instead of serializing its own launch.
struct PArgs {
    const float* in[6];
    const float* W[6];
    const float* b[6];
};

#define LDA 72
#define LDW 72
#define LDC 68

__global__ __launch_bounds__(256) void proj_hist_kernel(
    PArgs a, const int* __restrict__ ei, int n, int e, int nblk_proj) {
    __shared__ __align__(16) char sbuf[34816];

    int p   = blockIdx.y;
    int tid = threadIdx.x;

    // ---------------- histogram slice ----------------
    if (p == 6) {
        if (tid == 0 && blockIdx.x == 0) g_total = 0;
        int i = blockIdx.x * 256 + tid;       // thread handles 8 edges = 2 int4
        const int4* e4 = (const int4*)ei;     // rows live in ei[0..e)
        int ne4 = e >> 2;
        #pragma unroll
        for (int t = 0; t < 2; t++) {
            int idx4 = i * 2 + t;
            if (idx4 < ne4) {
                int4 r = __ldg(&e4[idx4]);
                if ((unsigned)r.x < (unsigned)n) atomicAdd(&g_cnt[r.x], 1);
                if ((unsigned)r.y < (unsigned)n) atomicAdd(&g_cnt[r.y], 1);
                if ((unsigned)r.z < (unsigned)n) atomicAdd(&g_cnt[r.z], 1);
                if ((unsigned)r.w < (unsigned)n) atomicAdd(&g_cnt[r.w], 1);
            } else if (idx4 == ne4) {
                for (int s = idx4 * 4; s < e; s++) {
                    int r = __ldg(&ei[s]);
                    if ((unsigned)r < (unsigned)n) atomicAdd(&g_cnt[r], 1);
                }
            }
        }
        return;
    }

    // ---------------- projection slices ----------------
    if (blockIdx.x >= nblk_proj) return;

    __half* sA = (__half*)sbuf;
    __half* sW = (__half*)(sbuf + 18432);
    float*  sC = (float*)sbuf;

    const float* in   = a.in[p];
    const float* W    = a.W[p];
    const float* bias = a.b[p];
    __half* outp;
    int coloff;
    switch (p) {
        case 0: outp = g_q; coloff = 0;  break;
        case 1: outp = g_k; coloff = 0;  break;
        case 2: outp = g_q; coloff = 64; break;
        case 3: outp = g_k; coloff = 64; break;
        case 4: outp = g_v; coloff = 0;  break;
        default: outp = g_v; coloff = 64; break;
    }

    int base = blockIdx.x * 128;

    #pragma unroll
    for (int t = 0; t < 8; t++) {
        int idx = tid + t * 256;
        int row = idx >> 4, c4 = idx & 15;
        int g = base + row;
        float4 f = (g < n) ? ((const float4*)in)[(size_t)g * 16 + c4]
                           : make_float4(0.f, 0.f, 0.f, 0.f);
        __half2 h0 = __floats2half2_rn(f.x, f.y);
        __half2 h1 = __floats2half2_rn(f.z, f.w);
        __half2* d = (__half2*)&sA[row * LDA + c4 * 4];
        d[0] = h0; d[1] = h1;
    }
    #pragma unroll
    for (int t = 0; t < 4; t++) {
        int idx = tid + t * 256;
        int row = idx >> 4, c4 = idx & 15;
        float4 f = ((const float4*)W)[idx];
        __half2 h0 = __floats2half2_rn(f.x, f.y);
        __half2 h1 = __floats2half2_rn(f.z, f.w);
        __half2* d = (__half2*)&sW[row * LDW + c4 * 4];
        d[0] = h0; d[1] = h1;
    }
    __syncthreads();

    int w  = tid >> 5;
    int wm = w & 3, wn = w >> 2;

    wmma::fragment<wmma::accumulator, 16, 16, 16, float> c[2][2];
    #pragma unroll
    for (int i = 0; i < 2; i++)
        #pragma unroll
        for (int jj = 0; jj < 2; jj++)
            wmma::fill_fragment(c[i][jj], 0.f);

    #pragma unroll
    for (int k0 = 0; k0 < 64; k0 += 16) {
        wmma::fragment<wmma::matrix_a, 16, 16, 16, __half, wmma::row_major> af[2];
        wmma::fragment<wmma::matrix_b, 16, 16, 16, __half, wmma::col_major> bf[2];
        #pragma unroll
        for (int i = 0; i < 2; i++)
            wmma::load_matrix_sync(af[i], &sA[(wm * 32 + i * 16) * LDA + k0], LDA);
        #pragma unroll
        for (int jj = 0; jj < 2; jj++)
            wmma::load_matrix_sync(bf[jj], &sW[(wn * 32 + jj * 16) * LDW + k0], LDW);
        #pragma unroll
        for (int i = 0; i < 2; i++)
            #pragma unroll
            for (int jj = 0; jj < 2; jj++)
                wmma::mma_sync(c[i][jj], af[i], bf[jj], c[i][jj]);
    }
    __syncthreads();

    #pragma unroll
    for (int i = 0; i < 2; i++)
        #pragma unroll
        for (int jj = 0; jj < 2; jj++)
            wmma::store_matrix_sync(&sC[(wm * 32 + i * 16) * LDC + wn * 32 + jj * 16],
                                    c[i][jj], LDC, wmma::mem_row_major);
    __syncthreads();

    #pragma unroll
    for (int t = 0; t < 16; t++) {
        int i = tid + t * 256;
        int row = i >> 5, pr = i & 31;
        int g = base + row;
        if (g < n) {
            float f0 = sC[row * LDC + 2 * pr];
            float f1 = sC[row * LDC + 2 * pr + 1];
            if (bias) { f0 += bias[2 * pr]; f1 += bias[2 * pr + 1]; }
            *(__half2*)&outp[(size_t)g * 128 + coloff + 2 * pr] =
                __floats2half2_rn(f0, f1);
        }
    }
}

// ---------------- kernel 2: one-shot atomic-ticket scan ----------------
// Block-local exclusive scan, base allocated via one global atomic ticket.
// Bucket regions land in arbitrary order — harmless for CSR.
__global__ __launch_bounds__(SCAN_BLK) void scan_ticket_kernel(int n) {
    __shared__ int s_w[8];
    __shared__ int s_tot;
    __shared__ int s_base;
    int tid = threadIdx.x;
    int i = blockIdx.x * SCAN_BLK + tid;
    int v = (i < n) ? g_cnt[i] : 0;
    if (i < n) g_cnt[i] = 0;                 // reset for next graph replay

    int x = v;
    #pragma unroll
    for (int o = 1; o < 32; o <<= 1) {
        int t = __shfl_up_sync(0xFFFFFFFFu, x, o);
        if ((tid & 31) >= o) x += t;
    }
    if ((tid & 31) == 31) s_w[tid >> 5] = x;
    __syncthreads();
    if (tid < 8) {
        int w = s_w[tid];
        #pragma unroll
        for (int o = 1; o < 8; o <<= 1) {
            int t = __shfl_up_sync(0xFFu, w, o);
            if (tid >= o) w += t;
        }
        s_w[tid] = w;
        if (tid == 7) s_tot = w;
    }
    __syncthreads();
    int warp = tid >> 5;
    int woff = (warp == 0) ? 0 : s_w[warp - 1];
    int excl = woff + x - v;

    if (tid == 0) s_base = atomicAdd(&g_total, s_tot);
    __syncthreads();

    if (i < n) {
        int g = s_base + excl;
        g_start[i]  = g;
        g_cursor[i] = g;
    }
}

// ---------------- kernel 3: bucket cols by destination (R6 1-wide) ------
__global__ void scatter_kernel(const int* __restrict__ ei, int e, int n) {
    int i = blockIdx.x * blockDim.x + threadIdx.x;
    if (i >= e) return;
    int r = __ldg(&ei[i]);
    int c = __ldg(&ei[e + i]);
    if ((unsigned)r >= (unsigned)n || (unsigned)c >= (unsigned)n) return;
    int pos = atomicAdd(&g_cursor[r], 1);
    g_sc[pos] = c;
}

// ---------------- kernel 4: per-node gather + softmax + aggregate --------
// One warp per destination node, 2 edges in flight (measured-best config).
// Lanes 0-15 alpha/t, 16-31 beta/x. Invalid slots -> ex forced to 0.
__global__ __launch_bounds__(256) void node_kernel(float* __restrict__ out, int n) {
    int warp = (blockIdx.x * blockDim.x + threadIdx.x) >> 5;
    int lane = threadIdx.x & 31;
    if (warp >= n) return;
    int r = warp;

    int j    = g_start[r];
    int jend = g_cursor[r];

    uint2 qu = ((const uint2*)(g_q + (size_t)r * 128))[lane];
    float2 q0 = __half22float2(*(const __half2*)&qu.x);
    float2 q1 = __half22float2(*(const __half2*)&qu.y);

    float4 acc = make_float4(0.f, 0.f, 0.f, 0.f);
    float  den = 0.f;

    uint2 kA = make_uint2(0,0), vA = make_uint2(0,0);
    uint2 kB = make_uint2(0,0), vB = make_uint2(0,0);
    if (j < jend) {
        int c = __ldg(&g_sc[j]);
        kA = ((const uint2*)(g_k + (size_t)c * 128))[lane];
        vA = ((const uint2*)(g_v + (size_t)c * 128))[lane];
    }
    if (j + 1 < jend) {
        int c = __ldg(&g_sc[j + 1]);
        kB = ((const uint2*)(g_k + (size_t)c * 128))[lane];
        vB = ((const uint2*)(g_v + (size_t)c * 128))[lane];
    }

    while (j < jend) {
        uint2 k0 = kA, v0 = vA, k1 = kB, v1 = vB;
        int rem = jend - j;
        int jn = j + 2;
        if (jn < jend) {
            int c = __ldg(&g_sc[jn]);
            kA = ((const uint2*)(g_k + (size_t)c * 128))[lane];
            vA = ((const uint2*)(g_v + (size_t)c * 128))[lane];
        }
        if (jn + 1 < jend) {
            int c = __ldg(&g_sc[jn + 1]);
            kB = ((const uint2*)(g_k + (size_t)c * 128))[lane];
            vB = ((const uint2*)(g_v + (size_t)c * 128))[lane];
        }
        j = jn;

        float2 ka0 = __half22float2(*(const __half2*)&k0.x);
        float2 ka1 = __half22float2(*(const __half2*)&k0.y);
        float2 kb0 = __half22float2(*(const __half2*)&k1.x);
        float2 kb1 = __half22float2(*(const __half2*)&k1.y);

        float p0 = q0.x * ka0.x + q0.y * ka0.y + q1.x * ka1.x + q1.y * ka1.y;
        float p1 = q0.x * kb0.x + q0.y * kb0.y + q1.x * kb1.x + q1.y * kb1.y;

        p0 += __shfl_xor_sync(0xFFFFFFFFu, p0, 1);
        p1 += __shfl_xor_sync(0xFFFFFFFFu, p1, 1);
        p0 += __shfl_xor_sync(0xFFFFFFFFu, p0, 2);
        p1 += __shfl_xor_sync(0xFFFFFFFFu, p1, 2);
        p0 += __shfl_xor_sync(0xFFFFFFFFu, p0, 4);
        p1 += __shfl_xor_sync(0xFFFFFFFFu, p1, 4);
        p0 += __shfl_xor_sync(0xFFFFFFFFu, p0, 8);
        p1 += __shfl_xor_sync(0xFFFFFFFFu, p1, 8);

        float ex0 = __expf(p0 * 0.125f);
        float ex1 = (rem > 1) ? __expf(p1 * 0.125f) : 0.f;
        den += ex0 + ex1;

        float2 va0 = __half22float2(*(const __half2*)&v0.x);
        float2 va1 = __half22float2(*(const __half2*)&v0.y);
        float2 vb0 = __half22float2(*(const __half2*)&v1.x);
        float2 vb1 = __half22float2(*(const __half2*)&v1.y);

        acc.x = fmaf(ex0, va0.x, fmaf(ex1, vb0.x, acc.x));
        acc.y = fmaf(ex0, va0.y, fmaf(ex1, vb0.y, acc.y));
        acc.z = fmaf(ex0, va1.x, fmaf(ex1, vb1.x, acc.z));
        acc.w = fmaf(ex0, va1.y, fmaf(ex1, vb1.y, acc.w));
    }

    float inv = (den > 0.f) ? __frcp_rn(den) : 0.f;
    acc.x *= inv; acc.y *= inv; acc.z *= inv; acc.w *= inv;

    int totD = n * D;
    if (lane < 16) {   // t-message -> out_t
        *(float4*)&out[totD + r * D + 4 * lane] = acc;
    } else {           // x-message -> out_x
        *(float4*)&out[r * D + 4 * (lane - 16)] = acc;
    }
}

// ---------------- launch ----------------
extern "C" void kernel_launch(void* const* d_in, const int* in_sizes, int n_in,
                              void* d_out, int out_size) {
    const float* x_src = (const float*)d_in[0];
    const float* x_tgt = (const float*)d_in[1];
    const float* t_src = (const float*)d_in[2];
    const float* t_tgt = (const float*)d_in[3];
    const int*   ei    = (const int*)d_in[4];
    const float* W_x  = (const float*)d_in[5];
    const float* W_t  = (const float*)d_in[6];
    const float* Ka_W = (const float*)d_in[7];
    const float* Ka_b = (const float*)d_in[8];
    const float* Qa_W = (const float*)d_in[9];
    const float* Qa_b = (const float*)d_in[10];
    const float* Kb_W = (const float*)d_in[11];
    const float* Kb_b = (const float*)d_in[12];
    const float* Qb_W = (const float*)d_in[13];
    const float* Qb_b = (const float*)d_in[14];

    int n = in_sizes[0] / D;      // 50000
    int e = in_sizes[4] / 2;      // 800000

    PArgs pa;
    pa.in[0] = t_tgt; pa.W[0] = Qa_W; pa.b[0] = Qa_b;    // q_alpha
    pa.in[1] = t_src; pa.W[1] = Ka_W; pa.b[1] = Ka_b;    // k_alpha
    pa.in[2] = x_tgt; pa.W[2] = Qb_W; pa.b[2] = Qb_b;    // q_beta
    pa.in[3] = x_src; pa.W[3] = Kb_W; pa.b[3] = Kb_b;    // k_beta
    pa.in[4] = t_src; pa.W[4] = W_t;  pa.b[4] = nullptr; // v_t
    pa.in[5] = x_src; pa.W[5] = W_x;  pa.b[5] = nullptr; // v_x

    int nblk_proj = (n + 127) / 128;                    // 391
    int nblk_hist = ((e + 7) / 8 + 255) / 256;          // 391 (8 edges/thread)
    int gx = nblk_proj > nblk_hist ? nblk_proj : nblk_hist;
    int nb = (n + SCAN_BLK - 1) / SCAN_BLK;             // 196

    proj_hist_kernel<<<dim3(gx, 7), 256>>>(pa, ei, n, e, nblk_proj);
    scan_ticket_kernel<<<nb, SCAN_BLK>>>(n);
    scatter_kernel<<<(e + 255) / 256, 256>>>(ei, e, n);
    node_kernel<<<(n * 32 + 255) / 256, 256>>>((float*)d_out, n);
}

// round 12
// speedup vs baseline: 1.2560x; 1.0189x over previous
#include <cuda_runtime.h>
#include <cuda_fp16.h>
#include <mma.h>
using namespace nvcuda;

#define D 64
#define N_MAX 50048
#define E_MAX 800000
#define SCAN_BLK 256

// ---------------- device scratch (static, allowed) ----------------
// Packed half tables: row = 128 halfs = 256B.
//   g_q[node] = [q_alpha(64) | q_beta(64)]
//   g_k[node] = [k_alpha(64) | k_beta(64)]
//   g_v[node] = [v_t(64)     | v_x(64)   ]
__device__ __align__(16) __half g_q[N_MAX * 128];
__device__ __align__(16) __half g_k[N_MAX * 128];
__device__ __align__(16) __half g_v[N_MAX * 128];

// CSR-style bucketing of edges by destination (row).
__device__ int g_cnt[N_MAX];      // in-degree (zero at load; scan re-zeros)
__device__ int g_start[N_MAX];    // bucket base
__device__ int g_cursor[N_MAX];   // bucket END (start + cnt), set by scan
__device__ int g_sc[E_MAX];       // col index per bucketed edge
__device__ int g_rank[E_MAX];     // within-bucket rank of each edge (from hist)
__device__ int g_total;           // ticket counter

// ---------------- kernel 1: projections via HMMA + fused histogram ------
// blockIdx.y 0..5: projections (tensor-bound). blockIdx.y == 6: histogram
// (atomic-latency bound) — hides under the tensor work. The histogram also
// records each edge's within-bucket rank so the scatter needs NO atomics.
struct PArgs {
    const float* in[6];
    const float* W[6];
    const float* b[6];
};

#define LDA 72
#define LDW 72
#define LDC 68

__global__ __launch_bounds__(256) void proj_hist_kernel(
    PArgs a, const int* __restrict__ ei, int n, int e, int nblk_proj) {
    __shared__ __align__(16) char sbuf[34816];

    int p   = blockIdx.y;
    int tid = threadIdx.x;

    // ---------------- histogram slice ----------------
    if (p == 6) {
        if (tid == 0 && blockIdx.x == 0) g_total = 0;
        int i = blockIdx.x * 256 + tid;       // thread handles 8 edges = 2 int4
        const int4* e4 = (const int4*)ei;
        int ne4 = e >> 2;
        #pragma unroll
        for (int t = 0; t < 2; t++) {
            int idx4 = i * 2 + t;
            if (idx4 < ne4) {
                int4 r = __ldg(&e4[idx4]);
                int b = idx4 * 4;
                if ((unsigned)r.x < (unsigned)n) g_rank[b + 0] = atomicAdd(&g_cnt[r.x], 1);
                if ((unsigned)r.y < (unsigned)n) g_rank[b + 1] = atomicAdd(&g_cnt[r.y], 1);
                if ((unsigned)r.z < (unsigned)n) g_rank[b + 2] = atomicAdd(&g_cnt[r.z], 1);
                if ((unsigned)r.w < (unsigned)n) g_rank[b + 3] = atomicAdd(&g_cnt[r.w], 1);
            } else if (idx4 == ne4) {
                for (int s = idx4 * 4; s < e; s++) {
                    int r = __ldg(&ei[s]);
                    if ((unsigned)r < (unsigned)n) g_rank[s] = atomicAdd(&g_cnt[r], 1);
                }
            }
        }
        return;
    }

    // ---------------- projection slices ----------------
    if (blockIdx.x >= nblk_proj) return;

    __half* sA = (__half*)sbuf;
    __half* sW = (__half*)(sbuf + 18432);
    float*  sC = (float*)sbuf;

    const float* in   = a.in[p];
    const float* W    = a.W[p];
    const float* bias = a.b[p];
    __half* outp;
    int coloff;
    switch (p) {
        case 0: outp = g_q; coloff = 0;  break;
        case 1: outp = g_k; coloff = 0;  break;
        case 2: outp = g_q; coloff = 64; break;
        case 3: outp = g_k; coloff = 64; break;
        case 4: outp = g_v; coloff = 0;  break;
        default: outp = g_v; coloff = 64; break;
    }

    int base = blockIdx.x * 128;

    #pragma unroll
    for (int t = 0; t < 8; t++) {
        int idx = tid + t * 256;
        int row = idx >> 4, c4 = idx & 15;
        int g = base + row;
        float4 f = (g < n) ? ((const float4*)in)[(size_t)g * 16 + c4]
                           : make_float4(0.f, 0.f, 0.f, 0.f);
        __half2 h0 = __floats2half2_rn(f.x, f.y);
        __half2 h1 = __floats2half2_rn(f.z, f.w);
        __half2* d = (__half2*)&sA[row * LDA + c4 * 4];
        d[0] = h0; d[1] = h1;
    }
    #pragma unroll
    for (int t = 0; t < 4; t++) {
        int idx = tid + t * 256;
        int row = idx >> 4, c4 = idx & 15;
        float4 f = ((const float4*)W)[idx];
        __half2 h0 = __floats2half2_rn(f.x, f.y);
        __half2 h1 = __floats2half2_rn(f.z, f.w);
        __half2* d = (__half2*)&sW[row * LDW + c4 * 4];
        d[0] = h0; d[1] = h1;
    }
    __syncthreads();

    int w  = tid >> 5;
    int wm = w & 3, wn = w >> 2;

    wmma::fragment<wmma::accumulator, 16, 16, 16, float> c[2][2];
    #pragma unroll
    for (int i = 0; i < 2; i++)
        #pragma unroll
        for (int jj = 0; jj < 2; jj++)
            wmma::fill_fragment(c[i][jj], 0.f);

    #pragma unroll
    for (int k0 = 0; k0 < 64; k0 += 16) {
        wmma::fragment<wmma::matrix_a, 16, 16, 16, __half, wmma::row_major> af[2];
        wmma::fragment<wmma::matrix_b, 16, 16, 16, __half, wmma::col_major> bf[2];
        #pragma unroll
        for (int i = 0; i < 2; i++)
            wmma::load_matrix_sync(af[i], &sA[(wm * 32 + i * 16) * LDA + k0], LDA);
        #pragma unroll
        for (int jj = 0; jj < 2; jj++)
            wmma::load_matrix_sync(bf[jj], &sW[(wn * 32 + jj * 16) * LDW + k0], LDW);
        #pragma unroll
        for (int i = 0; i < 2; i++)
            #pragma unroll
            for (int jj = 0; jj < 2; jj++)
                wmma::mma_sync(c[i][jj], af[i], bf[jj], c[i][jj]);
    }
    __syncthreads();

    #pragma unroll
    for (int i = 0; i < 2; i++)
        #pragma unroll
        for (int jj = 0; jj < 2; jj++)
            wmma::store_matrix_sync(&sC[(wm * 32 + i * 16) * LDC + wn * 32 + jj * 16],
                                    c[i][jj], LDC, wmma::mem_row_major);
    __syncthreads();

    #pragma unroll
    for (int t = 0; t < 16; t++) {
        int i = tid + t * 256;
        int row = i >> 5, pr = i & 31;
        int g = base + row;
        if (g < n) {
            float f0 = sC[row * LDC + 2 * pr];
            float f1 = sC[row * LDC + 2 * pr + 1];
            if (bias) { f0 += bias[2 * pr]; f1 += bias[2 * pr + 1]; }
            *(__half2*)&outp[(size_t)g * 128 + coloff + 2 * pr] =
                __floats2half2_rn(f0, f1);
        }
    }
}

// ---------------- kernel 2: one-shot atomic-ticket scan ----------------
// cursor now holds the bucket END (start + cnt) — scatter no longer bumps it.
__global__ __launch_bounds__(SCAN_BLK) void scan_ticket_kernel(int n) {
    __shared__ int s_w[8];
    __shared__ int s_tot;
    __shared__ int s_base;
    int tid = threadIdx.x;
    int i = blockIdx.x * SCAN_BLK + tid;
    int v = (i < n) ? g_cnt[i] : 0;
    if (i < n) g_cnt[i] = 0;                 // reset for next graph replay

    int x = v;
    #pragma unroll
    for (int o = 1; o < 32; o <<= 1) {
        int t = __shfl_up_sync(0xFFFFFFFFu, x, o);
        if ((tid & 31) >= o) x += t;
    }
    if ((tid & 31) == 31) s_w[tid >> 5] = x;
    __syncthreads();
    if (tid < 8) {
        int w = s_w[tid];
        #pragma unroll
        for (int o = 1; o < 8; o <<= 1) {
            int t = __shfl_up_sync(0xFFu, w, o);
            if (tid >= o) w += t;
        }
        s_w[tid] = w;
        if (tid == 7) s_tot = w;
    }
    __syncthreads();
    int warp = tid >> 5;
    int woff = (warp == 0) ? 0 : s_w[warp - 1];
    int excl = woff + x - v;

    if (tid == 0) s_base = atomicAdd(&g_total, s_tot);
    __syncthreads();

    if (i < n) {
        int g = s_base + excl;
        g_start[i]  = g;
        g_cursor[i] = g + v;    // bucket end
    }
}

// ---------------- kernel 3: atomic-free scatter ----------------
// pos = start[r] + precomputed rank. Pure loads + store -> full MLP.
__global__ void scatter_kernel(const int* __restrict__ ei, int e, int n) {
    int i = blockIdx.x * blockDim.x + threadIdx.x;
    if (i >= e) return;
    int r = __ldg(&ei[i]);
    int c = __ldg(&ei[e + i]);
    if ((unsigned)r >= (unsigned)n || (unsigned)c >= (unsigned)n) return;
    int pos = __ldg(&g_start[r]) + __ldg(&g_rank[i]);
    g_sc[pos] = c;
}

// ---------------- kernel 4: per-node gather + softmax + aggregate --------
// One warp per node, 2 edges in flight. 128-thread blocks (4 warps) to cut
// block-tail imbalance from degree variance. Score dot in HFMA2 (half2) with
// a single cvt per edge; fp32 shfl reduction; fp32 message accumulation.
__global__ __launch_bounds__(128) void node_kernel(float* __restrict__ out, int n) {
    int warp = (blockIdx.x * blockDim.x + threadIdx.x) >> 5;
    int lane = threadIdx.x & 31;
    if (warp >= n) return;
    int r = warp;

    int j    = g_start[r];
    int jend = g_cursor[r];

    // lane-hoisted base pointers (one IMAD.WIDE per gather afterwards)
    const uint2* kb = (const uint2*)g_k + lane;
    const uint2* vb = (const uint2*)g_v + lane;

    uint2 qu = ((const uint2*)(g_q + (size_t)r * 128))[lane];
    __half2 qh0 = *(const __half2*)&qu.x;
    __half2 qh1 = *(const __half2*)&qu.y;

    float4 acc = make_float4(0.f, 0.f, 0.f, 0.f);
    float  den = 0.f;

    uint2 kA = make_uint2(0,0), vA = make_uint2(0,0);
    uint2 kB = make_uint2(0,0), vB = make_uint2(0,0);
    if (j < jend) {
        size_t o = (size_t)__ldg(&g_sc[j]) * 32;
        kA = kb[o]; vA = vb[o];
    }
    if (j + 1 < jend) {
        size_t o = (size_t)__ldg(&g_sc[j + 1]) * 32;
        kB = kb[o]; vB = vb[o];
    }

    while (j < jend) {
        uint2 k0 = kA, v0 = vA, k1 = kB, v1 = vB;
        int rem = jend - j;
        int jn = j + 2;
        if (jn < jend) {
            size_t o = (size_t)__ldg(&g_sc[jn]) * 32;
            kA = kb[o]; vA = vb[o];
        }
        if (jn + 1 < jend) {
            size_t o = (size_t)__ldg(&g_sc[jn + 1]) * 32;
            kB = kb[o]; vB = vb[o];
        }
        j = jn;

        // per-lane dot in half2 (2 ops), single cvt, combine in fp32
        __half2 dA = __hmul2(qh0, *(const __half2*)&k0.x);
        dA = __hfma2(qh1, *(const __half2*)&k0.y, dA);
        __half2 dB = __hmul2(qh0, *(const __half2*)&k1.x);
        dB = __hfma2(qh1, *(const __half2*)&k1.y, dB);
        float2 fA = __half22float2(dA);
        float2 fB = __half22float2(dB);
        float p0 = fA.x + fA.y;
        float p1 = fB.x + fB.y;

        // two independent 16-lane fp32 reductions, interleaved for ILP
        p0 += __shfl_xor_sync(0xFFFFFFFFu, p0, 1);
        p1 += __shfl_xor_sync(0xFFFFFFFFu, p1, 1);
        p0 += __shfl_xor_sync(0xFFFFFFFFu, p0, 2);
        p1 += __shfl_xor_sync(0xFFFFFFFFu, p1, 2);
        p0 += __shfl_xor_sync(0xFFFFFFFFu, p0, 4);
        p1 += __shfl_xor_sync(0xFFFFFFFFu, p1, 4);
        p0 += __shfl_xor_sync(0xFFFFFFFFu, p0, 8);
        p1 += __shfl_xor_sync(0xFFFFFFFFu, p1, 8);

        float ex0 = __expf(p0 * 0.125f);
        float ex1 = (rem > 1) ? __expf(p1 * 0.125f) : 0.f;
        den += ex0 + ex1;

        float2 va0 = __half22float2(*(const __half2*)&v0.x);
        float2 va1 = __half22float2(*(const __half2*)&v0.y);
        float2 vb0 = __half22float2(*(const __half2*)&v1.x);
        float2 vb1 = __half22float2(*(const __half2*)&v1.y);

        acc.x = fmaf(ex0, va0.x, fmaf(ex1, vb0.x, acc.x));
        acc.y = fmaf(ex0, va0.y, fmaf(ex1, vb0.y, acc.y));
        acc.z = fmaf(ex0, va1.x, fmaf(ex1, vb1.x, acc.z));
        acc.w = fmaf(ex0, va1.y, fmaf(ex1, vb1.y, acc.w));
    }

    float inv = (den > 0.f) ? __frcp_rn(den) : 0.f;
    acc.x *= inv; acc.y *= inv; acc.z *= inv; acc.w *= inv;

    int totD = n * D;
    if (lane < 16) {   // t-message -> out_t
        *(float4*)&out[totD + r * D + 4 * lane] = acc;
    } else {           // x-message -> out_x
        *(float4*)&out[r * D + 4 * (lane - 16)] = acc;
    }
}

// ---------------- launch ----------------
extern "C" void kernel_launch(void* const* d_in, const int* in_sizes, int n_in,
                              void* d_out, int out_size) {
    const float* x_src = (const float*)d_in[0];
    const float* x_tgt = (const float*)d_in[1];
    const float* t_src = (const float*)d_in[2];
    const float* t_tgt = (const float*)d_in[3];
    const int*   ei    = (const int*)d_in[4];
    const float* W_x  = (const float*)d_in[5];
    const float* W_t  = (const float*)d_in[6];
    const float* Ka_W = (const float*)d_in[7];
    const float* Ka_b = (const float*)d_in[8];
    const float* Qa_W = (const float*)d_in[9];
    const float* Qa_b = (const float*)d_in[10];
    const float* Kb_W = (const float*)d_in[11];
    const float* Kb_b = (const float*)d_in[12];
    const float* Qb_W = (const float*)d_in[13];
    const float* Qb_b = (const float*)d_in[14];

    int n = in_sizes[0] / D;      // 50000
    int e = in_sizes[4] / 2;      // 800000

    PArgs pa;
    pa.in[0] = t_tgt; pa.W[0] = Qa_W; pa.b[0] = Qa_b;    // q_alpha
    pa.in[1] = t_src; pa.W[1] = Ka_W; pa.b[1] = Ka_b;    // k_alpha
    pa.in[2] = x_tgt; pa.W[2] = Qb_W; pa.b[2] = Qb_b;    // q_beta
    pa.in[3] = x_src; pa.W[3] = Kb_W; pa.b[3] = Kb_b;    // k_beta
    pa.in[4] = t_src; pa.W[4] = W_t;  pa.b[4] = nullptr; // v_t
    pa.in[5] = x_src; pa.W[5] = W_x;  pa.b[5] = nullptr; // v_x

    int nblk_proj = (n + 127) / 128;                    // 391
    int nblk_hist = ((e + 7) / 8 + 255) / 256;          // 391
    int gx = nblk_proj > nblk_hist ? nblk_proj : nblk_hist;
    int nb = (n + SCAN_BLK - 1) / SCAN_BLK;             // 196

    proj_hist_kernel<<<dim3(gx, 7), 256>>>(pa, ei, n, e, nblk_proj);
    scan_ticket_kernel<<<nb, SCAN_BLK>>>(n);
    scatter_kernel<<<(e + 255) / 256, 256>>>(ei, e, n);
    node_kernel<<<(n * 32 + 127) / 128, 128>>>((float*)d_out, n);
}

// round 13
// speedup vs baseline: 1.3041x; 1.0383x over previous
#include <cuda_runtime.h>
#include <cuda_fp16.h>
#include <mma.h>
using namespace nvcuda;

#define D 64
#define N_MAX 50048
#define E_MAX 800000
#define SCAN_BLK 256

// ---------------- device scratch (static, allowed) ----------------
// Packed half tables: row = 128 halfs = 256B.
//   g_q[node] = [q_alpha(64) | q_beta(64)]
//   g_k[node] = [k_alpha(64) | k_beta(64)]
//   g_v[node] = [v_t(64)     | v_x(64)   ]
__device__ __align__(16) __half g_q[N_MAX * 128];
__device__ __align__(16) __half g_k[N_MAX * 128];
__device__ __align__(16) __half g_v[N_MAX * 128];

// CSR-style bucketing of edges by destination (row).
__device__ int g_cnt[N_MAX];      // in-degree (zero at load; scan re-zeros)
__device__ int g_start[N_MAX];    // bucket base
__device__ int g_cursor[N_MAX];   // bucket END (start + cnt), set by scan
__device__ int g_sc[E_MAX];       // col index per bucketed edge
__device__ int g_rank[E_MAX];     // within-bucket rank of each edge (from hist)
__device__ int g_total;           // ticket counter

// ---------------- kernel 1: projections via HMMA + fused histogram ------
struct PArgs {
    const float* in[6];
    const float* W[6];
    const float* b[6];
};

#define LDA 72
#define LDW 72
#define LDC 68

__global__ __launch_bounds__(256) void proj_hist_kernel(
    PArgs a, const int* __restrict__ ei, int n, int e, int nblk_proj) {
    __shared__ __align__(16) char sbuf[34816];

    int p   = blockIdx.y;
    int tid = threadIdx.x;

    // ---------------- histogram slice (hides under tensor work) ----------
    if (p == 6) {
        if (tid == 0 && blockIdx.x == 0) g_total = 0;
        int i = blockIdx.x * 256 + tid;       // thread handles 8 edges = 2 int4
        const int4* e4 = (const int4*)ei;
        int ne4 = e >> 2;
        #pragma unroll
        for (int t = 0; t < 2; t++) {
            int idx4 = i * 2 + t;
            if (idx4 < ne4) {
                int4 r = __ldg(&e4[idx4]);
                int b = idx4 * 4;
                if ((unsigned)r.x < (unsigned)n) g_rank[b + 0] = atomicAdd(&g_cnt[r.x], 1);
                if ((unsigned)r.y < (unsigned)n) g_rank[b + 1] = atomicAdd(&g_cnt[r.y], 1);
                if ((unsigned)r.z < (unsigned)n) g_rank[b + 2] = atomicAdd(&g_cnt[r.z], 1);
                if ((unsigned)r.w < (unsigned)n) g_rank[b + 3] = atomicAdd(&g_cnt[r.w], 1);
            } else if (idx4 == ne4) {
                for (int s = idx4 * 4; s < e; s++) {
                    int r = __ldg(&ei[s]);
                    if ((unsigned)r < (unsigned)n) g_rank[s] = atomicAdd(&g_cnt[r], 1);
                }
            }
        }
        return;
    }

    // ---------------- projection slices ----------------
    if (blockIdx.x >= nblk_proj) return;

    __half* sA = (__half*)sbuf;
    __half* sW = (__half*)(sbuf + 18432);
    float*  sC = (float*)sbuf;

    const float* in   = a.in[p];
    const float* W    = a.W[p];
    const float* bias = a.b[p];
    __half* outp;
    int coloff;
    switch (p) {
        case 0: outp = g_q; coloff = 0;  break;
        case 1: outp = g_k; coloff = 0;  break;
        case 2: outp = g_q; coloff = 64; break;
        case 3: outp = g_k; coloff = 64; break;
        case 4: outp = g_v; coloff = 0;  break;
        default: outp = g_v; coloff = 64; break;
    }

    int base = blockIdx.x * 128;

    #pragma unroll
    for (int t = 0; t < 8; t++) {
        int idx = tid + t * 256;
        int row = idx >> 4, c4 = idx & 15;
        int g = base + row;
        float4 f = (g < n) ? ((const float4*)in)[(size_t)g * 16 + c4]
                           : make_float4(0.f, 0.f, 0.f, 0.f);
        __half2 h0 = __floats2half2_rn(f.x, f.y);
        __half2 h1 = __floats2half2_rn(f.z, f.w);
        __half2* d = (__half2*)&sA[row * LDA + c4 * 4];
        d[0] = h0; d[1] = h1;
    }
    #pragma unroll
    for (int t = 0; t < 4; t++) {
        int idx = tid + t * 256;
        int row = idx >> 4, c4 = idx & 15;
        float4 f = ((const float4*)W)[idx];
        __half2 h0 = __floats2half2_rn(f.x, f.y);
        __half2 h1 = __floats2half2_rn(f.z, f.w);
        __half2* d = (__half2*)&sW[row * LDW + c4 * 4];
        d[0] = h0; d[1] = h1;
    }
    __syncthreads();

    int w  = tid >> 5;
    int wm = w & 3, wn = w >> 2;

    wmma::fragment<wmma::accumulator, 16, 16, 16, float> c[2][2];
    #pragma unroll
    for (int i = 0; i < 2; i++)
        #pragma unroll
        for (int jj = 0; jj < 2; jj++)
            wmma::fill_fragment(c[i][jj], 0.f);

    #pragma unroll
    for (int k0 = 0; k0 < 64; k0 += 16) {
        wmma::fragment<wmma::matrix_a, 16, 16, 16, __half, wmma::row_major> af[2];
        wmma::fragment<wmma::matrix_b, 16, 16, 16, __half, wmma::col_major> bf[2];
        #pragma unroll
        for (int i = 0; i < 2; i++)
            wmma::load_matrix_sync(af[i], &sA[(wm * 32 + i * 16) * LDA + k0], LDA);
        #pragma unroll
        for (int jj = 0; jj < 2; jj++)
            wmma::load_matrix_sync(bf[jj], &sW[(wn * 32 + jj * 16) * LDW + k0], LDW);
        #pragma unroll
        for (int i = 0; i < 2; i++)
            #pragma unroll
            for (int jj = 0; jj < 2; jj++)
                wmma::mma_sync(c[i][jj], af[i], bf[jj], c[i][jj]);
    }
    __syncthreads();

    #pragma unroll
    for (int i = 0; i < 2; i++)
        #pragma unroll
        for (int jj = 0; jj < 2; jj++)
            wmma::store_matrix_sync(&sC[(wm * 32 + i * 16) * LDC + wn * 32 + jj * 16],
                                    c[i][jj], LDC, wmma::mem_row_major);
    __syncthreads();

    #pragma unroll
    for (int t = 0; t < 16; t++) {
        int i = tid + t * 256;
        int row = i >> 5, pr = i & 31;
        int g = base + row;
        if (g < n) {
            float f0 = sC[row * LDC + 2 * pr];
            float f1 = sC[row * LDC + 2 * pr + 1];
            if (bias) { f0 += bias[2 * pr]; f1 += bias[2 * pr + 1]; }
            *(__half2*)&outp[(size_t)g * 128 + coloff + 2 * pr] =
                __floats2half2_rn(f0, f1);
        }
    }
}

// ---------------- kernel 2: one-shot atomic-ticket scan ----------------
__global__ __launch_bounds__(SCAN_BLK) void scan_ticket_kernel(int n) {
    __shared__ int s_w[8];
    __shared__ int s_tot;
    __shared__ int s_base;
    int tid = threadIdx.x;
    int i = blockIdx.x * SCAN_BLK + tid;
    int v = (i < n) ? g_cnt[i] : 0;
    if (i < n) g_cnt[i] = 0;

    int x = v;
    #pragma unroll
    for (int o = 1; o < 32; o <<= 1) {
        int t = __shfl_up_sync(0xFFFFFFFFu, x, o);
        if ((tid & 31) >= o) x += t;
    }
    if ((tid & 31) == 31) s_w[tid >> 5] = x;
    __syncthreads();
    if (tid < 8) {
        int w = s_w[tid];
        #pragma unroll
        for (int o = 1; o < 8; o <<= 1) {
            int t = __shfl_up_sync(0xFFu, w, o);
            if (tid >= o) w += t;
        }
        s_w[tid] = w;
        if (tid == 7) s_tot = w;
    }
    __syncthreads();
    int warp = tid >> 5;
    int woff = (warp == 0) ? 0 : s_w[warp - 1];
    int excl = woff + x - v;

    if (tid == 0) s_base = atomicAdd(&g_total, s_tot);
    __syncthreads();

    if (i < n) {
        int g = s_base + excl;
        g_start[i]  = g;
        g_cursor[i] = g + v;    // bucket end
    }
}

// ---------------- kernel 3: atomic-free scatter ----------------
__global__ void scatter_kernel(const int* __restrict__ ei, int e, int n) {
    int i = blockIdx.x * blockDim.x + threadIdx.x;
    if (i >= e) return;
    int r = __ldg(&ei[i]);
    int c = __ldg(&ei[e + i]);
    if ((unsigned)r >= (unsigned)n || (unsigned)c >= (unsigned)n) return;
    int pos = __ldg(&g_start[r]) + __ldg(&g_rank[i]);
    g_sc[pos] = c;
}

// ---------------- kernel 4: per-node gather + softmax + aggregate --------
// One warp per node, 2 edges per iteration. Lane->work mapping amortizes
// the reduction: lanes 0-15 load edge A's k row (uint4 = 8 halfs each;
// lanes 0-7 = alpha dims, 8-15 = beta dims), lanes 16-31 edge B's. A single
// 3-step shfl_xor reduce (1,2,4) produces all four dots at once; two
// shfl_idx broadcasts deliver per-lane weights. 5 shfl / 2 edges (was 8).
__global__ __launch_bounds__(128) void node_kernel(float* __restrict__ out, int n) {
    int warp = (blockIdx.x * blockDim.x + threadIdx.x) >> 5;
    int lane = threadIdx.x & 31;
    if (warp >= n) return;
    int r = warp;

    int j    = g_start[r];
    int jend = g_cursor[r];

    int lane16 = lane & 15;
    int isB    = lane >> 4;           // 0 for edge-A lanes, 1 for edge-B lanes
    int srcA   = (lane & 16) >> 1;    // 0 or 8
    int srcB   = 16 + srcA;           // 16 or 24

    // q row: 16 uint4 per row; lanes 0-15 and 16-31 read the same data.
    uint4 qv = ((const uint4*)g_q)[(size_t)r * 16 + lane16];
    __half2 q0 = *(const __half2*)&qv.x;
    __half2 q1 = *(const __half2*)&qv.y;
    __half2 q2 = *(const __half2*)&qv.z;
    __half2 q3 = *(const __half2*)&qv.w;

    float4 acc = make_float4(0.f, 0.f, 0.f, 0.f);
    float  den = 0.f;

    // depth-1 pipeline over edge pairs
    uint4 kP = make_uint4(0, 0, 0, 0);
    uint2 vAP = make_uint2(0, 0), vBP = make_uint2(0, 0);
    if (j < jend) {
        int cA = __ldg(&g_sc[j]);
        int cB = (j + 1 < jend) ? __ldg(&g_sc[j + 1]) : cA;
        int cS = isB ? cB : cA;
        kP  = ((const uint4*)g_k)[(size_t)cS * 16 + lane16];
        vAP = ((const uint2*)g_v)[(size_t)cA * 32 + lane];
        vBP = ((const uint2*)g_v)[(size_t)cB * 32 + lane];
    }

    while (j < jend) {
        uint4 kv = kP;
        uint2 vA = vAP, vB = vBP;
        int rem = jend - j;
        int jn = j + 2;
        if (jn < jend) {
            int cA = __ldg(&g_sc[jn]);
            int cB = (jn + 1 < jend) ? __ldg(&g_sc[jn + 1]) : cA;
            int cS = isB ? cB : cA;
            kP  = ((const uint4*)g_k)[(size_t)cS * 16 + lane16];
            vAP = ((const uint2*)g_v)[(size_t)cA * 32 + lane];
            vBP = ((const uint2*)g_v)[(size_t)cB * 32 + lane];
        }
        j = jn;

        // 8-half dot fragment in half2, single cvt, fp32 combine
        __half2 d = __hmul2(q0, *(const __half2*)&kv.x);
        d = __hfma2(q1, *(const __half2*)&kv.y, d);
        d = __hfma2(q2, *(const __half2*)&kv.z, d);
        d = __hfma2(q3, *(const __half2*)&kv.w, d);
        float2 f = __half22float2(d);
        float p = f.x + f.y;

        // one 3-step reduce for all four dots (8-lane groups)
        p += __shfl_xor_sync(0xFFFFFFFFu, p, 1);
        p += __shfl_xor_sync(0xFFFFFFFFu, p, 2);
        p += __shfl_xor_sync(0xFFFFFFFFu, p, 4);

        float ex = __expf(p * 0.125f);

        // per-lane weights: lanes 0-15 want alpha-ex, 16-31 beta-ex
        float wA = __shfl_sync(0xFFFFFFFFu, ex, srcA);
        float wB = __shfl_sync(0xFFFFFFFFu, ex, srcB);
        if (rem < 2) wB = 0.f;
        den += wA + wB;

        float2 va0 = __half22float2(*(const __half2*)&vA.x);
        float2 va1 = __half22float2(*(const __half2*)&vA.y);
        float2 vb0 = __half22float2(*(const __half2*)&vB.x);
        float2 vb1 = __half22float2(*(const __half2*)&vB.y);

        acc.x = fmaf(wA, va0.x, fmaf(wB, vb0.x, acc.x));
        acc.y = fmaf(wA, va0.y, fmaf(wB, vb0.y, acc.y));
        acc.z = fmaf(wA, va1.x, fmaf(wB, vb1.x, acc.z));
        acc.w = fmaf(wA, va1.y, fmaf(wB, vb1.y, acc.w));
    }

    float inv = (den > 0.f) ? __frcp_rn(den) : 0.f;
    acc.x *= inv; acc.y *= inv; acc.z *= inv; acc.w *= inv;

    int totD = n * D;
    if (lane < 16) {   // t-message -> out_t
        *(float4*)&out[totD + r * D + 4 * lane] = acc;
    } else {           // x-message -> out_x
        *(float4*)&out[r * D + 4 * (lane - 16)] = acc;
    }
}

// ---------------- launch ----------------
extern "C" void kernel_launch(void* const* d_in, const int* in_sizes, int n_in,
                              void* d_out, int out_size) {
    const float* x_src = (const float*)d_in[0];
    const float* x_tgt = (const float*)d_in[1];
    const float* t_src = (const float*)d_in[2];
    const float* t_tgt = (const float*)d_in[3];
    const int*   ei    = (const int*)d_in[4];
    const float* W_x  = (const float*)d_in[5];
    const float* W_t  = (const float*)d_in[6];
    const float* Ka_W = (const float*)d_in[7];
    const float* Ka_b = (const float*)d_in[8];
    const float* Qa_W = (const float*)d_in[9];
    const float* Qa_b = (const float*)d_in[10];
    const float* Kb_W = (const float*)d_in[11];
    const float* Kb_b = (const float*)d_in[12];
    const float* Qb_W = (const float*)d_in[13];
    const float* Qb_b = (const float*)d_in[14];

    int n = in_sizes[0] / D;      // 50000
    int e = in_sizes[4] / 2;      // 800000

    PArgs pa;
    pa.in[0] = t_tgt; pa.W[0] = Qa_W; pa.b[0] = Qa_b;    // q_alpha
    pa.in[1] = t_src; pa.W[1] = Ka_W; pa.b[1] = Ka_b;    // k_alpha
    pa.in[2] = x_tgt; pa.W[2] = Qb_W; pa.b[2] = Qb_b;    // q_beta
    pa.in[3] = x_src; pa.W[3] = Kb_W; pa.b[3] = Kb_b;    // k_beta
    pa.in[4] = t_src; pa.W[4] = W_t;  pa.b[4] = nullptr; // v_t
    pa.in[5] = x_src; pa.W[5] = W_x;  pa.b[5] = nullptr; // v_x

    int nblk_proj = (n + 127) / 128;                    // 391
    int nblk_hist = ((e + 7) / 8 + 255) / 256;          // 391
    int gx = nblk_proj > nblk_hist ? nblk_proj : nblk_hist;
    int nb = (n + SCAN_BLK - 1) / SCAN_BLK;             // 196

    proj_hist_kernel<<<dim3(gx, 7), 256>>>(pa, ei, n, e, nblk_proj);
    scan_ticket_kernel<<<nb, SCAN_BLK>>>(n);
    scatter_kernel<<<(e + 255) / 256, 256>>>(ei, e, n);
    node_kernel<<<(n * 32 + 127) / 128, 128>>>((float*)d_out, n);
}

// round 14
// speedup vs baseline: 1.3435x; 1.0302x over previous
#include <cuda_runtime.h>
#include <cuda_fp16.h>
#include <mma.h>
using namespace nvcuda;

#define D 64
#define N_MAX 50048
#define E_MAX 800000
#define SCAN_BLK 256

// ---------------- device scratch (static, allowed) ----------------
// g_q[node]  = [q_alpha(64) | q_beta(64)]                      (256B row)
// g_kv[node] = [k_alpha(64) | k_beta(64) | v_t(64) | v_x(64)]  (512B row)
__device__ __align__(16) __half g_q [N_MAX * 128];
__device__ __align__(16) __half g_kv[N_MAX * 256];

// CSR-style bucketing of edges by destination (row).
__device__ int g_cnt[N_MAX];      // in-degree (zero at load; scan re-zeros)
__device__ int g_start[N_MAX];    // bucket base
__device__ int g_cursor[N_MAX];   // bucket END (start + cnt), set by scan
__device__ int g_sc[E_MAX + 8];   // BYTE OFFSET of src node's kv row (c<<9)
__device__ int g_rank[E_MAX];     // within-bucket rank (from hist)
__device__ int g_total;           // ticket counter

// ---------------- kernel 1: projections via HMMA + fused histogram ------
struct PArgs {
    const float* in[6];
    const float* W[6];
    const float* b[6];
};

#define LDA 72
#define LDW 72
#define LDC 68

__global__ __launch_bounds__(256) void proj_hist_kernel(
    PArgs a, const int* __restrict__ ei, int n, int e, int nblk_proj) {
    __shared__ __align__(16) char sbuf[34816];

    int p   = blockIdx.y;
    int tid = threadIdx.x;

    // ---------------- histogram slice (hides under tensor work) ----------
    if (p == 6) {
        if (tid == 0 && blockIdx.x == 0) g_total = 0;
        int i = blockIdx.x * 256 + tid;       // thread handles 8 edges = 2 int4
        const int4* e4 = (const int4*)ei;
        int ne4 = e >> 2;
        #pragma unroll
        for (int t = 0; t < 2; t++) {
            int idx4 = i * 2 + t;
            if (idx4 < ne4) {
                int4 r = __ldg(&e4[idx4]);
                int b = idx4 * 4;
                if ((unsigned)r.x < (unsigned)n) g_rank[b + 0] = atomicAdd(&g_cnt[r.x], 1);
                if ((unsigned)r.y < (unsigned)n) g_rank[b + 1] = atomicAdd(&g_cnt[r.y], 1);
                if ((unsigned)r.z < (unsigned)n) g_rank[b + 2] = atomicAdd(&g_cnt[r.z], 1);
                if ((unsigned)r.w < (unsigned)n) g_rank[b + 3] = atomicAdd(&g_cnt[r.w], 1);
            } else if (idx4 == ne4) {
                for (int s = idx4 * 4; s < e; s++) {
                    int r = __ldg(&ei[s]);
                    if ((unsigned)r < (unsigned)n) g_rank[s] = atomicAdd(&g_cnt[r], 1);
                }
            }
        }
        return;
    }

    // ---------------- projection slices ----------------
    if (blockIdx.x >= nblk_proj) return;

    __half* sA = (__half*)sbuf;
    __half* sW = (__half*)(sbuf + 18432);
    float*  sC = (float*)sbuf;

    const float* in   = a.in[p];
    const float* W    = a.W[p];
    const float* bias = a.b[p];
    __half* outp;
    int coloff, stride;
    switch (p) {
        case 0: outp = g_q;  coloff = 0;   stride = 128; break;  // q_alpha
        case 1: outp = g_kv; coloff = 0;   stride = 256; break;  // k_alpha
        case 2: outp = g_q;  coloff = 64;  stride = 128; break;  // q_beta
        case 3: outp = g_kv; coloff = 64;  stride = 256; break;  // k_beta
        case 4: outp = g_kv; coloff = 128; stride = 256; break;  // v_t
        default: outp = g_kv; coloff = 192; stride = 256; break; // v_x
    }

    int base = blockIdx.x * 128;

    #pragma unroll
    for (int t = 0; t < 8; t++) {
        int idx = tid + t * 256;
        int row = idx >> 4, c4 = idx & 15;
        int g = base + row;
        float4 f = (g < n) ? ((const float4*)in)[(size_t)g * 16 + c4]
                           : make_float4(0.f, 0.f, 0.f, 0.f);
        __half2 h0 = __floats2half2_rn(f.x, f.y);
        __half2 h1 = __floats2half2_rn(f.z, f.w);
        __half2* d = (__half2*)&sA[row * LDA + c4 * 4];
        d[0] = h0; d[1] = h1;
    }
    #pragma unroll
    for (int t = 0; t < 4; t++) {
        int idx = tid + t * 256;
        int row = idx >> 4, c4 = idx & 15;
        float4 f = ((const float4*)W)[idx];
        __half2 h0 = __floats2half2_rn(f.x, f.y);
        __half2 h1 = __floats2half2_rn(f.z, f.w);
        __half2* d = (__half2*)&sW[row * LDW + c4 * 4];
        d[0] = h0; d[1] = h1;
    }
    __syncthreads();

    int w  = tid >> 5;
    int wm = w & 3, wn = w >> 2;

    wmma::fragment<wmma::accumulator, 16, 16, 16, float> c[2][2];
    #pragma unroll
    for (int i = 0; i < 2; i++)
        #pragma unroll
        for (int jj = 0; jj < 2; jj++)
            wmma::fill_fragment(c[i][jj], 0.f);

    #pragma unroll
    for (int k0 = 0; k0 < 64; k0 += 16) {
        wmma::fragment<wmma::matrix_a, 16, 16, 16, __half, wmma::row_major> af[2];
        wmma::fragment<wmma::matrix_b, 16, 16, 16, __half, wmma::col_major> bf[2];
        #pragma unroll
        for (int i = 0; i < 2; i++)
            wmma::load_matrix_sync(af[i], &sA[(wm * 32 + i * 16) * LDA + k0], LDA);
        #pragma unroll
        for (int jj = 0; jj < 2; jj++)
            wmma::load_matrix_sync(bf[jj], &sW[(wn * 32 + jj * 16) * LDW + k0], LDW);
        #pragma unroll
        for (int i = 0; i < 2; i++)
            #pragma unroll
            for (int jj = 0; jj < 2; jj++)
                wmma::mma_sync(c[i][jj], af[i], bf[jj], c[i][jj]);
    }
    __syncthreads();

    #pragma unroll
    for (int i = 0; i < 2; i++)
        #pragma unroll
        for (int jj = 0; jj < 2; jj++)
            wmma::store_matrix_sync(&sC[(wm * 32 + i * 16) * LDC + wn * 32 + jj * 16],
                                    c[i][jj], LDC, wmma::mem_row_major);
    __syncthreads();

    #pragma unroll
    for (int t = 0; t < 16; t++) {
        int i = tid + t * 256;
        int row = i >> 5, pr = i & 31;
        int g = base + row;
        if (g < n) {
            float f0 = sC[row * LDC + 2 * pr];
            float f1 = sC[row * LDC + 2 * pr + 1];
            if (bias) { f0 += bias[2 * pr]; f1 += bias[2 * pr + 1]; }
            *(__half2*)&outp[(size_t)g * stride + coloff + 2 * pr] =
                __floats2half2_rn(f0, f1);
        }
    }
}

// ---------------- kernel 2: one-shot atomic-ticket scan ----------------
__global__ __launch_bounds__(SCAN_BLK) void scan_ticket_kernel(int n) {
    __shared__ int s_w[8];
    __shared__ int s_tot;
    __shared__ int s_base;
    int tid = threadIdx.x;
    int i = blockIdx.x * SCAN_BLK + tid;
    int v = (i < n) ? g_cnt[i] : 0;
    if (i < n) g_cnt[i] = 0;

    int x = v;
    #pragma unroll
    for (int o = 1; o < 32; o <<= 1) {
        int t = __shfl_up_sync(0xFFFFFFFFu, x, o);
        if ((tid & 31) >= o) x += t;
    }
    if ((tid & 31) == 31) s_w[tid >> 5] = x;
    __syncthreads();
    if (tid < 8) {
        int w = s_w[tid];
        #pragma unroll
        for (int o = 1; o < 8; o <<= 1) {
            int t = __shfl_up_sync(0xFFu, w, o);
            if (tid >= o) w += t;
        }
        s_w[tid] = w;
        if (tid == 7) s_tot = w;
    }
    __syncthreads();
    int warp = tid >> 5;
    int woff = (warp == 0) ? 0 : s_w[warp - 1];
    int excl = woff + x - v;

    if (tid == 0) s_base = atomicAdd(&g_total, s_tot);
    __syncthreads();

    if (i < n) {
        int g = s_base + excl;
        g_start[i]  = g;
        g_cursor[i] = g + v;    // bucket end
    }
}

// ---------------- kernel 3: atomic-free scatter (stores byte offsets) ----
__global__ void scatter_kernel(const int* __restrict__ ei, int e, int n) {
    int i = blockIdx.x * blockDim.x + threadIdx.x;
    if (i >= e) return;
    int r = __ldg(&ei[i]);
    int c = __ldg(&ei[e + i]);
    if ((unsigned)r >= (unsigned)n || (unsigned)c >= (unsigned)n) return;
    int pos = __ldg(&g_start[r]) + __ldg(&g_rank[i]);
    g_sc[pos] = c << 9;       // byte offset of kv row (512B rows)
}

// ---------------- kernel 4: per-node gather + softmax + aggregate --------
// One warp per node, 2 edges per iteration, 8-lane-group reduction
// (5 shfl / 2 edges). g_sc holds BYTE offsets: per-edge addressing is one
// IADD from the kv base; lane offsets are loop-invariant.
__global__ __launch_bounds__(128) void node_kernel(float* __restrict__ out, int n) {
    int warp = (blockIdx.x * blockDim.x + threadIdx.x) >> 5;
    int lane = threadIdx.x & 31;
    if (warp >= n) return;
    int r = warp;

    int j    = g_start[r];
    int jend = g_cursor[r];

    int lane16 = lane & 15;
    int isB    = lane >> 4;           // 0: edge-A lanes, 1: edge-B lanes
    int srcA   = (lane & 16) >> 1;    // 0 or 8
    int srcB   = 16 + srcA;           // 16 or 24

    const char* kvb = (const char*)g_kv;
    int koff = lane16 * 16;           // lane's 16B slice of the k part
    int voff = 256 + lane * 8;        // lane's 8B slice of the v part

    uint4 qv = ((const uint4*)g_q)[(size_t)r * 16 + lane16];
    __half2 q0 = *(const __half2*)&qv.x;
    __half2 q1 = *(const __half2*)&qv.y;
    __half2 q2 = *(const __half2*)&qv.z;
    __half2 q3 = *(const __half2*)&qv.w;

    float4 acc = make_float4(0.f, 0.f, 0.f, 0.f);
    float  den = 0.f;

    uint4 kP = make_uint4(0, 0, 0, 0);
    uint2 vAP = make_uint2(0, 0), vBP = make_uint2(0, 0);
    if (j < jend) {
        int offA = __ldg(&g_sc[j]);
        int offB = (j + 1 < jend) ? __ldg(&g_sc[j + 1]) : offA;
        int offS = isB ? offB : offA;
        kP  = *(const uint4*)(kvb + offS + koff);
        vAP = *(const uint2*)(kvb + offA + voff);
        vBP = *(const uint2*)(kvb + offB + voff);
    }

    while (j < jend) {
        uint4 kv = kP;
        uint2 vA = vAP, vB = vBP;
        int rem = jend - j;
        int jn = j + 2;
        if (jn < jend) {
            int offA = __ldg(&g_sc[jn]);
            int offB = (jn + 1 < jend) ? __ldg(&g_sc[jn + 1]) : offA;
            int offS = isB ? offB : offA;
            kP  = *(const uint4*)(kvb + offS + koff);
            vAP = *(const uint2*)(kvb + offA + voff);
            vBP = *(const uint2*)(kvb + offB + voff);
        }
        j = jn;

        // 8-half dot fragment in half2, single cvt, fp32 combine
        __half2 d = __hmul2(q0, *(const __half2*)&kv.x);
        d = __hfma2(q1, *(const __half2*)&kv.y, d);
        d = __hfma2(q2, *(const __half2*)&kv.z, d);
        d = __hfma2(q3, *(const __half2*)&kv.w, d);
        float2 f = __half22float2(d);
        float p = f.x + f.y;

        // one 3-step reduce for all four dots (8-lane groups)
        p += __shfl_xor_sync(0xFFFFFFFFu, p, 1);
        p += __shfl_xor_sync(0xFFFFFFFFu, p, 2);
        p += __shfl_xor_sync(0xFFFFFFFFu, p, 4);

        float ex = __expf(p * 0.125f);

        float wA = __shfl_sync(0xFFFFFFFFu, ex, srcA);
        float wB = __shfl_sync(0xFFFFFFFFu, ex, srcB);
        if (rem < 2) wB = 0.f;
        den += wA + wB;

        float2 va0 = __half22float2(*(const __half2*)&vA.x);
        float2 va1 = __half22float2(*(const __half2*)&vA.y);
        float2 vb0 = __half22float2(*(const __half2*)&vB.x);
        float2 vb1 = __half22float2(*(const __half2*)&vB.y);

        acc.x = fmaf(wA, va0.x, fmaf(wB, vb0.x, acc.x));
        acc.y = fmaf(wA, va0.y, fmaf(wB, vb0.y, acc.y));
        acc.z = fmaf(wA, va1.x, fmaf(wB, vb1.x, acc.z));
        acc.w = fmaf(wA, va1.y, fmaf(wB, vb1.y, acc.w));
    }

    float inv = (den > 0.f) ? __frcp_rn(den) : 0.f;
    acc.x *= inv; acc.y *= inv; acc.z *= inv; acc.w *= inv;

    int totD = n * D;
    if (lane < 16) {   // t-message -> out_t
        *(float4*)&out[totD + r * D + 4 * lane] = acc;
    } else {           // x-message -> out_x
        *(float4*)&out[r * D + 4 * (lane - 16)] = acc;
    }
}

// ---------------- launch ----------------
extern "C" void kernel_launch(void* const* d_in, const int* in_sizes, int n_in,
                              void* d_out, int out_size) {
    const float* x_src = (const float*)d_in[0];
    const float* x_tgt = (const float*)d_in[1];
    const float* t_src = (const float*)d_in[2];
    const float* t_tgt = (const float*)d_in[3];
    const int*   ei    = (const int*)d_in[4];
    const float* W_x  = (const float*)d_in[5];
    const float* W_t  = (const float*)d_in[6];
    const float* Ka_W = (const float*)d_in[7];
    const float* Ka_b = (const float*)d_in[8];
    const float* Qa_W = (const float*)d_in[9];
    const float* Qa_b = (const float*)d_in[10];
    const float* Kb_W = (const float*)d_in[11];
    const float* Kb_b = (const float*)d_in[12];
    const float* Qb_W = (const float*)d_in[13];
    const float* Qb_b = (const float*)d_in[14];

    int n = in_sizes[0] / D;      // 50000
    int e = in_sizes[4] / 2;      // 800000

    PArgs pa;
    pa.in[0] = t_tgt; pa.W[0] = Qa_W; pa.b[0] = Qa_b;    // q_alpha
    pa.in[1] = t_src; pa.W[1] = Ka_W; pa.b[1] = Ka_b;    // k_alpha
    pa.in[2] = x_tgt; pa.W[2] = Qb_W; pa.b[2] = Qb_b;    // q_beta
    pa.in[3] = x_src; pa.W[3] = Kb_W; pa.b[3] = Kb_b;    // k_beta
    pa.in[4] = t_src; pa.W[4] = W_t;  pa.b[4] = nullptr; // v_t
    pa.in[5] = x_src; pa.W[5] = W_x;  pa.b[5] = nullptr; // v_x

    int nblk_proj = (n + 127) / 128;                    // 391
    int nblk_hist = ((e + 7) / 8 + 255) / 256;          // 391
    int gx = nblk_proj > nblk_hist ? nblk_proj : nblk_hist;
    int nb = (n + SCAN_BLK - 1) / SCAN_BLK;             // 196

    proj_hist_kernel<<<dim3(gx, 7), 256>>>(pa, ei, n, e, nblk_proj);
    scan_ticket_kernel<<<nb, SCAN_BLK>>>(n);
    scatter_kernel<<<(e + 255) / 256, 256>>>(ei, e, n);
    node_kernel<<<(n * 32 + 127) / 128, 128>>>((float*)d_out, n);
}